// round 12
// baseline (speedup 1.0000x reference)
#include <cuda_runtime.h>
#include <cuda_bf16.h>
#include <cstdint>

// ---------------- problem constants ----------------
#define BB      8
#define QL      16
#define NHAT    16
#define HDIM    64
#define HID     1024
#define PASTLEN 8192
#define TOTKV   8208            // PASTLEN + QL
#define NSPLIT  16
#define SPLITBASE 512           // 8 chunks of 64; split 15 takes +16 tail
#define CHUNK2  64
#define NWARP   8
#define KSPLIT  8
#define KSLICE  (HID / KSPLIT)  // 128

// ---------------- device scratch (no allocation allowed) ----------------
__device__ float g_q  [BB*NHAT*QL*HDIM];                    // pre-scaled by 0.125
__device__ float g_k  [BB*NHAT*QL*HDIM];                    // new K rows
__device__ float g_v  [BB*NHAT*QL*HDIM];                    // new V rows
__device__ float g_qkv_pp[KSPLIT*128*3072];                 // qkv split-K partials
__device__ float g_op_pp [KSPLIT*128*HID];                  // oproj split-K partials
__device__ float g_part_acc[BB*NHAT*NSPLIT*QL*HDIM];        // per-split PV partials
__device__ float g_part_m  [BB*NHAT*NSPLIT*QL];
__device__ float g_part_l  [BB*NHAT*NSPLIT*QL];
__device__ float g_mid [BB*QL*HID];                         // permuted attn output

// ---------------- tf32 helpers ----------------
__device__ __forceinline__ uint32_t f2tf(float f) {
    uint32_t u;
    asm("cvt.rna.tf32.f32 %0, %1;" : "=r"(u) : "f"(f));
    return u;
}
__device__ __forceinline__ void mma_tf32(float& c0, float& c1, float& c2, float& c3,
    uint32_t a0, uint32_t a1, uint32_t a2, uint32_t a3, uint32_t b0, uint32_t b1)
{
    asm("mma.sync.aligned.m16n8k8.row.col.f32.tf32.tf32.f32 "
        "{%0,%1,%2,%3}, {%4,%5,%6,%7}, {%8,%9}, {%0,%1,%2,%3};"
        : "+f"(c0), "+f"(c1), "+f"(c2), "+f"(c3)
        : "r"(a0), "r"(a1), "r"(a2), "r"(a3), "r"(b0), "r"(b1));
}

// ============================================================
// Kernel 1a: fused QKV projection, split-K partial.
// ============================================================
__global__ __launch_bounds__(256) void qkv_part_kernel(
    const float* __restrict__ A,
    const float* __restrict__ Wq, const float* __restrict__ Wk,
    const float* __restrict__ Wv)
{
    __shared__ float As[64][17];
    __shared__ float Ws[64][17];

    const int tid = threadIdx.x;
    const int tx = tid & 15, ty = tid >> 4;
    const int col0 = blockIdx.x * 64;
    const int row0 = blockIdx.y * 64;
    const int ks   = blockIdx.z;
    const int mat  = col0 >> 10;
    const int f0   = col0 & 1023;
    const float* W = (mat == 0) ? Wq : (mat == 1) ? Wk : Wv;

    float acc[4][4];
#pragma unroll
    for (int r = 0; r < 4; r++)
#pragma unroll
        for (int c = 0; c < 4; c++) acc[r][c] = 0.f;

    const int lr = tid >> 2;
    const int lk = (tid & 3) * 4;
    const float* Arow = A + (size_t)(row0 + lr) * HID + ks*KSLICE + lk;
    const float* Wrow = W + (size_t)(f0  + lr) * HID + ks*KSLICE + lk;

    float4 a4 = *(const float4*)Arow;
    float4 w4 = *(const float4*)Wrow;

    for (int t = 0; t < KSLICE/16; t++) {
        As[lr][lk] = a4.x; As[lr][lk+1] = a4.y; As[lr][lk+2] = a4.z; As[lr][lk+3] = a4.w;
        Ws[lr][lk] = w4.x; Ws[lr][lk+1] = w4.y; Ws[lr][lk+2] = w4.z; Ws[lr][lk+3] = w4.w;
        __syncthreads();
        if (t < KSLICE/16 - 1) {
            a4 = *(const float4*)(Arow + (t+1)*16);
            w4 = *(const float4*)(Wrow + (t+1)*16);
        }
#pragma unroll
        for (int kk = 0; kk < 16; kk++) {
            float av[4], wv[4];
#pragma unroll
            for (int r = 0; r < 4; r++) av[r] = As[ty*4 + r][kk];
#pragma unroll
            for (int c = 0; c < 4; c++) wv[c] = Ws[tx*4 + c][kk];
#pragma unroll
            for (int r = 0; r < 4; r++)
#pragma unroll
                for (int c = 0; c < 4; c++) acc[r][c] += av[r] * wv[c];
        }
        __syncthreads();
    }

#pragma unroll
    for (int r = 0; r < 4; r++) {
        const int m = row0 + ty*4 + r;
        float4 o = make_float4(acc[r][0], acc[r][1], acc[r][2], acc[r][3]);
        *(float4*)&g_qkv_pp[((size_t)ks*128 + m)*3072 + col0 + tx*4] = o;
    }
}

// ============================================================
// Kernel 1b: reduce qkv split-K partials + bias -> [b][h][i][d]
// ============================================================
__global__ __launch_bounds__(256) void qkv_reduce_kernel(
    const float* __restrict__ bq, const float* __restrict__ bk,
    const float* __restrict__ bv)
{
    const int idx = blockIdx.x * 256 + threadIdx.x;
    const int m = idx / 768;
    const int f = (idx - m*768) * 4;
    const size_t base = (size_t)m*3072 + f;

    float4 s = *(const float4*)&g_qkv_pp[base];
#pragma unroll
    for (int ks = 1; ks < KSPLIT; ks++) {
        float4 p = *(const float4*)&g_qkv_pp[(size_t)ks*128*3072 + base];
        s.x += p.x; s.y += p.y; s.z += p.z; s.w += p.w;
    }

    const int mat = f >> 10;
    const int fl  = f & 1023;
    const float* bias = (mat == 0) ? bq : (mat == 1) ? bk : bv;
    s.x += bias[fl]; s.y += bias[fl+1]; s.z += bias[fl+2]; s.w += bias[fl+3];

    const int b = m >> 4, iq = m & 15;
    const int h = fl >> 6, d = fl & 63;
    const int dst = ((b*NHAT + h)*QL + iq)*HDIM + d;
    if (mat == 0) {
        s.x *= 0.125f; s.y *= 0.125f; s.z *= 0.125f; s.w *= 0.125f;
        *(float4*)&g_q[dst] = s;
    } else if (mat == 1) {
        *(float4*)&g_k[dst] = s;
    } else {
        *(float4*)&g_v[dst] = s;
    }
}

// ============================================================
// Kernel 2: flash attention, tf32 MMA, depth-2 register prefetch,
// block-level partial merge. grid = BB*NHAT*NSPLIT, block = 256.
// ============================================================
__global__ __launch_bounds__(256) void attn_mma_kernel(
    const float* __restrict__ past_k,
    const float* __restrict__ past_v,
    const float* __restrict__ padmask)
{
    // overlaid smem pool: Q/K/V tiles during mainloop, merge buffers after.
    __shared__ __align__(16) uint32_t SM[10048];          // 40.2 KB
    uint32_t (*Qs)[68] = (uint32_t(*)[68])(SM);           // [16][68]
    uint32_t (*Ks)[68] = (uint32_t(*)[68])(SM + 1088);    // [64][68]
    uint32_t (*Vs)[72] = (uint32_t(*)[72])(SM + 5440);    // [64][72]
    float* mrg_acc = (float*)SM;                          // [8][16][64]
    float* mrg_m   = (float*)(SM + 8192);                 // [8][16]
    float* mrg_l   = (float*)(SM + 8320);                 // [8][16]

    const int t    = threadIdx.x;
    const int lane = t & 31;
    const int w    = t >> 5;
    const int bh   = blockIdx.x >> 4;
    const int sp   = blockIdx.x & (NSPLIT - 1);
    const int b    = bh >> 4;
    const int s0   = sp * SPLITBASE;
    const int s1   = (sp == NSPLIT-1) ? TOTKV : s0 + SPLITBASE;

    const float4* pk4 = (const float4*)past_k;
    const float4* pv4 = (const float4*)past_v;
    const float4* gk4 = (const float4*)g_k;
    const float4* gv4 = (const float4*)g_v;

    // ---- stage Q (tf32) ----
    {
        float4 q4 = ((const float4*)g_q)[bh*256 + t];
        const int row = t >> 4, c = (t & 15) * 4;
        Qs[row][c]   = f2tf(q4.x);
        Qs[row][c+1] = f2tf(q4.y);
        Qs[row][c+2] = f2tf(q4.z);
        Qs[row][c+3] = f2tf(q4.w);
    }

    const int g   = lane >> 2;     // query row base
    const int tig = lane & 3;      // thread-in-group
    const int r0  = w * 8;         // this warp's kv-row base within chunk
    const int ldrow = t >> 4, ldc = t & 15;   // cooperative-load ids

    float m1 = -1e30f, m2 = -1e30f, l1 = 0.f, l2 = 0.f;
    float acc[8][4];
#pragma unroll
    for (int nt = 0; nt < 8; nt++)
#pragma unroll
        for (int c = 0; c < 4; c++) acc[nt][c] = 0.f;

    // ---- register load helper ----
    auto load_regs = [&](float4* kr, float4* vr, int base) {
        if (base >= s1) return;
        const int nrows = min(CHUNK2, s1 - base);
#pragma unroll
        for (int it = 0; it < 4; it++) {
            const int row = ldrow + it*16;
            const int gr = base + row;
            kr[it] = make_float4(0.f,0.f,0.f,0.f);
            vr[it] = make_float4(0.f,0.f,0.f,0.f);
            if (row < nrows) {
                if (gr < PASTLEN) {
                    kr[it] = pk4[(size_t)(bh*PASTLEN + gr)*16 + ldc];
                    vr[it] = pv4[(size_t)(bh*PASTLEN + gr)*16 + ldc];
                } else {
                    kr[it] = gk4[(bh*QL + (gr - PASTLEN))*16 + ldc];
                    vr[it] = gv4[(bh*QL + (gr - PASTLEN))*16 + ldc];
                }
            }
        }
    };

    // ---- vectorized tf32 smem store of a prefetched chunk ----
    auto store_chunk = [&](const float4* kr, const float4* vr) {
        const int c4 = ldc * 4;
#pragma unroll
        for (int it = 0; it < 4; it++) {
            const int row = ldrow + it*16;
            uint4 kk, vv;
            kk.x = f2tf(kr[it].x); kk.y = f2tf(kr[it].y);
            kk.z = f2tf(kr[it].z); kk.w = f2tf(kr[it].w);
            vv.x = f2tf(vr[it].x); vv.y = f2tf(vr[it].y);
            vv.z = f2tf(vr[it].z); vv.w = f2tf(vr[it].w);
            *(uint4*)&Ks[row][c4] = kk;
            *(uint4*)&Vs[row][c4] = vv;
        }
    };

    // ---- per-chunk compute (reads Ks/Vs/Qs) ----
    auto compute_chunk = [&](int c0) {
        // scores: S_w(16q x 8kv) = Q x K_w^T
        float s0r = 0.f, s1r = 0.f, s2r = 0.f, s3r = 0.f;
#pragma unroll
        for (int kt = 0; kt < 8; kt++) {
            const int k0 = kt * 8;
            uint32_t a0 = Qs[g][k0 + tig];
            uint32_t a1 = Qs[g+8][k0 + tig];
            uint32_t a2 = Qs[g][k0 + tig + 4];
            uint32_t a3 = Qs[g+8][k0 + tig + 4];
            uint32_t b0 = Ks[r0 + g][k0 + tig];
            uint32_t b1 = Ks[r0 + g][k0 + tig + 4];
            mma_tf32(s0r, s1r, s2r, s3r, a0, a1, a2, a3, b0, b1);
        }

        // masks
        const int jA = c0 + r0 + 2*tig;
        const int jB = jA + 1;
        const int iA = g, iB = g + 8;
        const bool vA = jA < s1, vB = jB < s1;
        const float pA = vA ? padmask[b*TOTKV + jA] * (-1e9f) : 0.f;
        const float pB = vB ? padmask[b*TOTKV + jB] * (-1e9f) : 0.f;
        s0r = vA ? s0r + pA + ((jA > PASTLEN + iA) ? -1e9f : 0.f) : -1e30f;
        s1r = vB ? s1r + pB + ((jB > PASTLEN + iA) ? -1e9f : 0.f) : -1e30f;
        s2r = vA ? s2r + pA + ((jA > PASTLEN + iB) ? -1e9f : 0.f) : -1e30f;
        s3r = vB ? s3r + pB + ((jB > PASTLEN + iB) ? -1e9f : 0.f) : -1e30f;

        // per-warp online softmax (4-lane row groups)
        float mxA = fmaxf(s0r, s1r);
        float mxB = fmaxf(s2r, s3r);
        mxA = fmaxf(mxA, __shfl_xor_sync(0xffffffffu, mxA, 1));
        mxA = fmaxf(mxA, __shfl_xor_sync(0xffffffffu, mxA, 2));
        mxB = fmaxf(mxB, __shfl_xor_sync(0xffffffffu, mxB, 1));
        mxB = fmaxf(mxB, __shfl_xor_sync(0xffffffffu, mxB, 2));

        const float mn1 = fmaxf(m1, mxA);
        const float mn2 = fmaxf(m2, mxB);
        const float cor1 = __expf(m1 - mn1);
        const float cor2 = __expf(m2 - mn2);
        const float p0 = __expf(s0r - mn1);
        const float p1 = __expf(s1r - mn1);
        const float p2 = __expf(s2r - mn2);
        const float p3 = __expf(s3r - mn2);
        float ls1 = p0 + p1;
        float ls2 = p2 + p3;
        ls1 += __shfl_xor_sync(0xffffffffu, ls1, 1);
        ls1 += __shfl_xor_sync(0xffffffffu, ls1, 2);
        ls2 += __shfl_xor_sync(0xffffffffu, ls2, 1);
        ls2 += __shfl_xor_sync(0xffffffffu, ls2, 2);
        l1 = l1 * cor1 + ls1;  m1 = mn1;
        l2 = l2 * cor2 + ls2;  m2 = mn2;

#pragma unroll
        for (int nt = 0; nt < 8; nt++) {
            acc[nt][0] *= cor1; acc[nt][1] *= cor1;
            acc[nt][2] *= cor2; acc[nt][3] *= cor2;
        }

        // P (C-frag) -> A-frag via shfl, cvt to tf32
        const uint32_t u0 = f2tf(p0), u1 = f2tf(p1), u2 = f2tf(p2), u3 = f2tf(p3);
        const int src0 = (lane & ~3) | (tig >> 1);
        const int src2 = src0 + 2;
        const uint32_t x0 = __shfl_sync(0xffffffffu, u0, src0);
        const uint32_t x1 = __shfl_sync(0xffffffffu, u1, src0);
        const uint32_t y0 = __shfl_sync(0xffffffffu, u0, src2);
        const uint32_t y1 = __shfl_sync(0xffffffffu, u1, src2);
        const uint32_t z0 = __shfl_sync(0xffffffffu, u2, src0);
        const uint32_t z1 = __shfl_sync(0xffffffffu, u2, src2);
        const uint32_t q0 = __shfl_sync(0xffffffffu, u3, src0);
        const uint32_t q1 = __shfl_sync(0xffffffffu, u3, src2);
        const uint32_t pa0 = (tig & 1) ? x1 : x0;
        const uint32_t pa2 = (tig & 1) ? y1 : y0;
        const uint32_t pa1 = (tig & 1) ? q0 : z0;
        const uint32_t pa3 = (tig & 1) ? q1 : z1;

        // PV: acc += P_w x V_w
#pragma unroll
        for (int nt = 0; nt < 8; nt++) {
            const int d0 = nt * 8;
            uint32_t b0 = Vs[r0 + tig][d0 + g];
            uint32_t b1 = Vs[r0 + tig + 4][d0 + g];
            mma_tf32(acc[nt][0], acc[nt][1], acc[nt][2], acc[nt][3],
                     pa0, pa1, pa2, pa3, b0, b1);
        }
    };

    // ---- depth-2 prefetch: two register buffer sets ----
    float4 krA[4], vrA[4], krB[4], vrB[4];
    load_regs(krA, vrA, s0);
    load_regs(krB, vrB, s0 + CHUNK2);

    for (int c0 = s0; c0 < s1; c0 += 2*CHUNK2) {
        // ---- even chunk (buffer A) ----
        __syncthreads();                 // prior compute done reading smem
        store_chunk(krA, vrA);
        __syncthreads();
        load_regs(krA, vrA, c0 + 2*CHUNK2);   // 2 chunks ahead
        compute_chunk(c0);

        // ---- odd chunk (buffer B) ----
        if (c0 + CHUNK2 < s1) {
            __syncthreads();
            store_chunk(krB, vrB);
            __syncthreads();
            load_regs(krB, vrB, c0 + 3*CHUNK2);
            compute_chunk(c0 + CHUNK2);
        }
    }

    // ================= block-level merge (smem overlay) =================
    __syncthreads();   // all warps done reading K/V/Q smem

#pragma unroll
    for (int nt = 0; nt < 8; nt++) {
        const int d = nt*8 + 2*tig;
        mrg_acc[(w*QL + g)  *HDIM + d]     = acc[nt][0];
        mrg_acc[(w*QL + g)  *HDIM + d + 1] = acc[nt][1];
        mrg_acc[(w*QL + g+8)*HDIM + d]     = acc[nt][2];
        mrg_acc[(w*QL + g+8)*HDIM + d + 1] = acc[nt][3];
    }
    if (tig == 0) {
        mrg_m[w*QL + g]     = m1;  mrg_m[w*QL + g + 8] = m2;
        mrg_l[w*QL + g]     = l1;  mrg_l[w*QL + g + 8] = l2;
    }
    __syncthreads();

    // thread t -> (q = t>>4, dg = t&15): merge 8 warps, write one float4
    {
        const int q = t >> 4, dg = t & 15;
        float mg = -1e30f;
#pragma unroll
        for (int ww = 0; ww < NWARP; ww++)
            mg = fmaxf(mg, mrg_m[ww*QL + q]);
        float L = 0.f;
        float4 a = make_float4(0.f, 0.f, 0.f, 0.f);
#pragma unroll
        for (int ww = 0; ww < NWARP; ww++) {
            const float wgt = __expf(mrg_m[ww*QL + q] - mg);
            L += mrg_l[ww*QL + q] * wgt;
            const float4 v = *(const float4*)&mrg_acc[(ww*QL + q)*HDIM + dg*4];
            a.x += v.x*wgt; a.y += v.y*wgt; a.z += v.z*wgt; a.w += v.w*wgt;
        }
        const int pb = blockIdx.x;               // bh*NSPLIT + sp
        *(float4*)&g_part_acc[((size_t)pb*QL + q)*HDIM + dg*4] = a;
        if (dg == 0) {
            g_part_m[pb*QL + q] = mg;
            g_part_l[pb*QL + q] = L;
        }
    }
}

// ============================================================
// Kernel 3: combine 16 split partials per bh -> permuted mid layout.
// ============================================================
__global__ __launch_bounds__(256) void combine_kernel()
{
    const int bh = blockIdx.x;
    const int b = bh >> 4, h = bh & 15;
    const int t = threadIdx.x;
    const int i = t >> 4, dg = t & 15;

    float mg = -1e30f;
#pragma unroll
    for (int sp = 0; sp < NSPLIT; sp++)
        mg = fmaxf(mg, g_part_m[(bh*NSPLIT + sp)*QL + i]);

    float L = 0.f;
    float4 acc = make_float4(0.f, 0.f, 0.f, 0.f);
#pragma unroll
    for (int sp = 0; sp < NSPLIT; sp++) {
        const int pi = (bh*NSPLIT + sp)*QL + i;
        const float wgt = __expf(g_part_m[pi] - mg);
        L += g_part_l[pi] * wgt;
        const float4 a = *(const float4*)&g_part_acc[(size_t)pi*HDIM + dg*4];
        acc.x += a.x * wgt; acc.y += a.y * wgt; acc.z += a.z * wgt; acc.w += a.w * wgt;
    }
    const float inv = 1.f / L;
    const float v[4] = {acc.x*inv, acc.y*inv, acc.z*inv, acc.w*inv};
#pragma unroll
    for (int k = 0; k < 4; k++) {
        const int d = dg*4 + k;
        g_mid[b*(QL*HID) + (d >> 2)*HID + (d & 3)*256 + i*16 + h] = v[k];
    }
}

// ============================================================
// Kernel 4a: output projection split-K partial.
// ============================================================
__global__ __launch_bounds__(256) void oproj_part_kernel(
    const float* __restrict__ Wo)
{
    __shared__ float As[64][17];
    __shared__ float Ws[64][17];

    const int tid = threadIdx.x;
    const int tx = tid & 15, ty = tid >> 4;
    const int col0 = blockIdx.x * 64;
    const int row0 = blockIdx.y * 64;
    const int ks   = blockIdx.z;

    float acc[4][4];
#pragma unroll
    for (int r = 0; r < 4; r++)
#pragma unroll
        for (int c = 0; c < 4; c++) acc[r][c] = 0.f;

    const int lr = tid >> 2;
    const int lk = (tid & 3) * 4;
    const float* Arow = g_mid + (size_t)(row0 + lr) * HID + ks*KSLICE + lk;
    const float* Wrow = Wo    + (size_t)(col0 + lr) * HID + ks*KSLICE + lk;

    float4 a4 = *(const float4*)Arow;
    float4 w4 = *(const float4*)Wrow;

    for (int t = 0; t < KSLICE/16; t++) {
        As[lr][lk] = a4.x; As[lr][lk+1] = a4.y; As[lr][lk+2] = a4.z; As[lr][lk+3] = a4.w;
        Ws[lr][lk] = w4.x; Ws[lr][lk+1] = w4.y; Ws[lr][lk+2] = w4.z; Ws[lr][lk+3] = w4.w;
        __syncthreads();
        if (t < KSLICE/16 - 1) {
            a4 = *(const float4*)(Arow + (t+1)*16);
            w4 = *(const float4*)(Wrow + (t+1)*16);
        }
#pragma unroll
        for (int kk = 0; kk < 16; kk++) {
            float av[4], wv[4];
#pragma unroll
            for (int r = 0; r < 4; r++) av[r] = As[ty*4 + r][kk];
#pragma unroll
            for (int c = 0; c < 4; c++) wv[c] = Ws[tx*4 + c][kk];
#pragma unroll
            for (int r = 0; r < 4; r++)
#pragma unroll
                for (int c = 0; c < 4; c++) acc[r][c] += av[r] * wv[c];
        }
        __syncthreads();
    }

#pragma unroll
    for (int r = 0; r < 4; r++) {
        const int m = row0 + ty*4 + r;
        float4 o = make_float4(acc[r][0], acc[r][1], acc[r][2], acc[r][3]);
        *(float4*)&g_op_pp[((size_t)ks*128 + m)*HID + col0 + tx*4] = o;
    }
}

// ============================================================
// Kernel 4b: reduce oproj partials + bias -> out.
// ============================================================
__global__ __launch_bounds__(256) void oproj_reduce_kernel(
    const float* __restrict__ bo, float* __restrict__ out)
{
    const int idx = blockIdx.x * 256 + threadIdx.x;
    const int m = idx >> 8;
    const int n = (idx & 255) * 4;
    const size_t base = (size_t)m*HID + n;

    float4 s = *(const float4*)&g_op_pp[base];
#pragma unroll
    for (int ks = 1; ks < KSPLIT; ks++) {
        float4 p = *(const float4*)&g_op_pp[(size_t)ks*128*HID + base];
        s.x += p.x; s.y += p.y; s.z += p.z; s.w += p.w;
    }
    s.x += bo[n]; s.y += bo[n+1]; s.z += bo[n+2]; s.w += bo[n+3];
    *(float4*)&out[base] = s;
}

// ============================================================
extern "C" void kernel_launch(void* const* d_in, const int* in_sizes, int n_in,
                              void* d_out, int out_size)
{
    const float* hidden  = (const float*)d_in[0];
    const float* past_k  = (const float*)d_in[1];
    const float* past_v  = (const float*)d_in[2];
    // d_in[3] causal_mask: computed analytically (j > PASTLEN + i)
    const float* padmask = (const float*)d_in[4];
    const float* Wq = (const float*)d_in[5];
    const float* bq = (const float*)d_in[6];
    const float* Wk = (const float*)d_in[7];
    const float* bk = (const float*)d_in[8];
    const float* Wv = (const float*)d_in[9];
    const float* bv = (const float*)d_in[10];
    const float* Wo = (const float*)d_in[11];
    const float* bo = (const float*)d_in[12];
    float* out = (float*)d_out;

    qkv_part_kernel<<<dim3(48, 2, KSPLIT), 256>>>(hidden, Wq, Wk, Wv);
    qkv_reduce_kernel<<<384, 256>>>(bq, bk, bv);
    attn_mma_kernel<<<BB*NHAT*NSPLIT, 256>>>(past_k, past_v, padmask);
    combine_kernel<<<BB*NHAT, 256>>>();
    oproj_part_kernel<<<dim3(16, 2, KSPLIT), 256>>>(Wo);
    oproj_reduce_kernel<<<128, 256>>>(bo, out);
}

// round 13
// speedup vs baseline: 1.0115x; 1.0115x over previous
#include <cuda_runtime.h>
#include <cuda_bf16.h>
#include <cstdint>

// ---------------- problem constants ----------------
#define BB      8
#define QL      16
#define NHAT    16
#define HDIM    64
#define HID     1024
#define PASTLEN 8192
#define TOTKV   8208            // PASTLEN + QL
#define NSPLIT  16
#define SPLITBASE 512           // 8 chunks of 64; split 15 takes +16 tail
#define CHUNK2  64
#define NWARP   8
#define STAGES  4
#define KSPLIT  4
#define KSLICE  (HID / KSPLIT)  // 256

// attn dynamic smem layout (bytes)
#define QS_BYTES   (QL*68*4)                 // 4352
#define KS_STRIDE  68
#define VS_STRIDE  72
#define KS_STAGE_B (CHUNK2*KS_STRIDE*4)      // 17408
#define VS_STAGE_B (CHUNK2*VS_STRIDE*4)      // 18432
#define KS_BYTES   (STAGES*KS_STAGE_B)       // 69632
#define VS_BYTES   (STAGES*VS_STAGE_B)       // 73728
#define ATTN_SMEM  (QS_BYTES + KS_BYTES + VS_BYTES)   // 147712

// ---------------- device scratch (no allocation allowed) ----------------
__device__ float g_q  [BB*NHAT*QL*HDIM];                    // pre-scaled by 0.125
__device__ float g_k  [BB*NHAT*QL*HDIM];                    // new K rows
__device__ float g_v  [BB*NHAT*QL*HDIM];                    // new V rows
__device__ float g_qkv_pp[KSPLIT*128*3072];                 // qkv split-K partials
__device__ float g_op_pp [KSPLIT*128*HID];                  // oproj split-K partials
__device__ float g_part_acc[BB*NHAT*NSPLIT*QL*HDIM];        // per-split PV partials
__device__ float g_part_m  [BB*NHAT*NSPLIT*QL];
__device__ float g_part_l  [BB*NHAT*NSPLIT*QL];
__device__ float g_mid [BB*QL*HID];                         // permuted attn output

// ---------------- helpers ----------------
__device__ __forceinline__ uint32_t f2tf(float f) {
    uint32_t u;
    asm("cvt.rna.tf32.f32 %0, %1;" : "=r"(u) : "f"(f));
    return u;
}
__device__ __forceinline__ void mma_tf32(float& c0, float& c1, float& c2, float& c3,
    uint32_t a0, uint32_t a1, uint32_t a2, uint32_t a3, uint32_t b0, uint32_t b1)
{
    asm("mma.sync.aligned.m16n8k8.row.col.f32.tf32.tf32.f32 "
        "{%0,%1,%2,%3}, {%4,%5,%6,%7}, {%8,%9}, {%0,%1,%2,%3};"
        : "+f"(c0), "+f"(c1), "+f"(c2), "+f"(c3)
        : "r"(a0), "r"(a1), "r"(a2), "r"(a3), "r"(b0), "r"(b1));
}
__device__ __forceinline__ uint32_t smem_u32(const void* p) {
    uint32_t a;
    asm("{ .reg .u64 t; cvta.to.shared.u64 t, %1; cvt.u32.u64 %0, t; }"
        : "=r"(a) : "l"(p));
    return a;
}
__device__ __forceinline__ void cp_async16(uint32_t dst, const void* src) {
    asm volatile("cp.async.cg.shared.global [%0], [%1], 16;" :: "r"(dst), "l"(src));
}
__device__ __forceinline__ void cp_commit() {
    asm volatile("cp.async.commit_group;" ::: "memory");
}

// ============================================================
// Kernel 1a: fused QKV projection, split-K partial.
// ============================================================
__global__ __launch_bounds__(256) void qkv_part_kernel(
    const float* __restrict__ A,
    const float* __restrict__ Wq, const float* __restrict__ Wk,
    const float* __restrict__ Wv)
{
    __shared__ float As[64][17];
    __shared__ float Ws[64][17];

    const int tid = threadIdx.x;
    const int tx = tid & 15, ty = tid >> 4;
    const int col0 = blockIdx.x * 64;
    const int row0 = blockIdx.y * 64;
    const int ks   = blockIdx.z;
    const int mat  = col0 >> 10;
    const int f0   = col0 & 1023;
    const float* W = (mat == 0) ? Wq : (mat == 1) ? Wk : Wv;

    float acc[4][4];
#pragma unroll
    for (int r = 0; r < 4; r++)
#pragma unroll
        for (int c = 0; c < 4; c++) acc[r][c] = 0.f;

    const int lr = tid >> 2;
    const int lk = (tid & 3) * 4;
    const float* Arow = A + (size_t)(row0 + lr) * HID + ks*KSLICE + lk;
    const float* Wrow = W + (size_t)(f0  + lr) * HID + ks*KSLICE + lk;

    float4 a4 = *(const float4*)Arow;
    float4 w4 = *(const float4*)Wrow;

    for (int t = 0; t < KSLICE/16; t++) {
        As[lr][lk] = a4.x; As[lr][lk+1] = a4.y; As[lr][lk+2] = a4.z; As[lr][lk+3] = a4.w;
        Ws[lr][lk] = w4.x; Ws[lr][lk+1] = w4.y; Ws[lr][lk+2] = w4.z; Ws[lr][lk+3] = w4.w;
        __syncthreads();
        if (t < KSLICE/16 - 1) {
            a4 = *(const float4*)(Arow + (t+1)*16);
            w4 = *(const float4*)(Wrow + (t+1)*16);
        }
#pragma unroll
        for (int kk = 0; kk < 16; kk++) {
            float av[4], wv[4];
#pragma unroll
            for (int r = 0; r < 4; r++) av[r] = As[ty*4 + r][kk];
#pragma unroll
            for (int c = 0; c < 4; c++) wv[c] = Ws[tx*4 + c][kk];
#pragma unroll
            for (int r = 0; r < 4; r++)
#pragma unroll
                for (int c = 0; c < 4; c++) acc[r][c] += av[r] * wv[c];
        }
        __syncthreads();
    }

#pragma unroll
    for (int r = 0; r < 4; r++) {
        const int m = row0 + ty*4 + r;
        float4 o = make_float4(acc[r][0], acc[r][1], acc[r][2], acc[r][3]);
        *(float4*)&g_qkv_pp[((size_t)ks*128 + m)*3072 + col0 + tx*4] = o;
    }
}

// ============================================================
// Kernel 1b: reduce qkv split-K partials + bias -> [b][h][i][d]
// ============================================================
__global__ __launch_bounds__(256) void qkv_reduce_kernel(
    const float* __restrict__ bq, const float* __restrict__ bk,
    const float* __restrict__ bv)
{
    const int idx = blockIdx.x * 256 + threadIdx.x;
    const int m = idx / 768;
    const int f = (idx - m*768) * 4;
    const size_t base = (size_t)m*3072 + f;

    float4 s = *(const float4*)&g_qkv_pp[base];
#pragma unroll
    for (int ks = 1; ks < KSPLIT; ks++) {
        float4 p = *(const float4*)&g_qkv_pp[(size_t)ks*128*3072 + base];
        s.x += p.x; s.y += p.y; s.z += p.z; s.w += p.w;
    }

    const int mat = f >> 10;
    const int fl  = f & 1023;
    const float* bias = (mat == 0) ? bq : (mat == 1) ? bk : bv;
    s.x += bias[fl]; s.y += bias[fl+1]; s.z += bias[fl+2]; s.w += bias[fl+3];

    const int b = m >> 4, iq = m & 15;
    const int h = fl >> 6, d = fl & 63;
    const int dst = ((b*NHAT + h)*QL + iq)*HDIM + d;
    if (mat == 0) {
        s.x *= 0.125f; s.y *= 0.125f; s.z *= 0.125f; s.w *= 0.125f;
        *(float4*)&g_q[dst] = s;
    } else if (mat == 1) {
        *(float4*)&g_k[dst] = s;
    } else {
        *(float4*)&g_v[dst] = s;
    }
}

// ============================================================
// Kernel 2: flash attention, tf32 MMA, 4-stage cp.async pipeline,
// block-level partial merge. grid = BB*NHAT*NSPLIT, block = 256.
// ============================================================
__global__ __launch_bounds__(256) void attn_mma_kernel(
    const float* __restrict__ past_k,
    const float* __restrict__ past_v,
    const float* __restrict__ padmask)
{
    extern __shared__ __align__(16) char dynsm[];
    uint32_t* Qs  = (uint32_t*)dynsm;                       // [16][68] tf32
    float*    KsB = (float*)(dynsm + QS_BYTES);             // [4][64][68] fp32
    float*    VsB = (float*)(dynsm + QS_BYTES + KS_BYTES);  // [4][64][72] fp32
    // epilogue overlay (into Ks region, after final sync)
    float* mrg_acc = (float*)(dynsm + QS_BYTES);            // [8][16][64]
    float* mrg_m   = mrg_acc + NWARP*QL*HDIM;               // [8][16]
    float* mrg_l   = mrg_m + NWARP*QL;

    const int t    = threadIdx.x;
    const int lane = t & 31;
    const int w    = t >> 5;
    const int bh   = blockIdx.x >> 4;
    const int sp   = blockIdx.x & (NSPLIT - 1);
    const int b    = bh >> 4;
    const int s0   = sp * SPLITBASE;
    const int s1   = (sp == NSPLIT-1) ? TOTKV : s0 + SPLITBASE;

    const float4* pk4 = (const float4*)past_k;
    const float4* pv4 = (const float4*)past_v;
    const float4* gk4 = (const float4*)g_k;
    const float4* gv4 = (const float4*)g_v;

    // ---- stage Q (tf32) ----
    {
        float4 q4 = ((const float4*)g_q)[bh*256 + t];
        const int row = t >> 4, c = (t & 15) * 4;
        Qs[row*KS_STRIDE + c]   = f2tf(q4.x);
        Qs[row*KS_STRIDE + c+1] = f2tf(q4.y);
        Qs[row*KS_STRIDE + c+2] = f2tf(q4.z);
        Qs[row*KS_STRIDE + c+3] = f2tf(q4.w);
    }

    const int g   = lane >> 2;     // query row base
    const int tig = lane & 3;      // thread-in-group
    const int r0  = w * 8;         // this warp's kv-row base within chunk
    const int ldrow = t >> 4, ldc = t & 15;   // cooperative-load ids

    const uint32_t ks_sm = smem_u32(KsB);
    const uint32_t vs_sm = smem_u32(VsB);

    float m1 = -1e30f, m2 = -1e30f, l1 = 0.f, l2 = 0.f;
    float acc[8][4];
#pragma unroll
    for (int nt = 0; nt < 8; nt++)
#pragma unroll
        for (int c = 0; c < 4; c++) acc[nt][c] = 0.f;

    // ---- issue cp.async for one chunk into its ring stage ----
    auto issue_chunk = [&](int ci) {
        const int base = s0 + ci*CHUNK2;
        if (base < s1) {
            const int stage = ci & (STAGES-1);
            const int nrows = min(CHUNK2, s1 - base);
            const uint32_t kst = ks_sm + stage*KS_STAGE_B + ldc*16;
            const uint32_t vst = vs_sm + stage*VS_STAGE_B + ldc*16;
#pragma unroll
            for (int it = 0; it < 4; it++) {
                const int row = ldrow + it*16;
                if (row < nrows) {
                    const int gr = base + row;
                    const float4 *ksrc, *vsrc;
                    if (gr < PASTLEN) {
                        ksrc = pk4 + (size_t)(bh*PASTLEN + gr)*16 + ldc;
                        vsrc = pv4 + (size_t)(bh*PASTLEN + gr)*16 + ldc;
                    } else {
                        ksrc = gk4 + (size_t)(bh*QL + (gr - PASTLEN))*16 + ldc;
                        vsrc = gv4 + (size_t)(bh*QL + (gr - PASTLEN))*16 + ldc;
                    }
                    cp_async16(kst + row*(KS_STRIDE*4), ksrc);
                    cp_async16(vst + row*(VS_STRIDE*4), vsrc);
                }
            }
        }
        cp_commit();   // always commit (possibly empty) to keep group count uniform
    };

    // ---- per-chunk compute (reads stage buffers; cvt to tf32 at use) ----
    auto compute_chunk = [&](int c0, int stage) {
        const float* Kst = KsB + stage*(CHUNK2*KS_STRIDE);
        const float* Vst = VsB + stage*(CHUNK2*VS_STRIDE);

        // scores: S_w(16q x 8kv) = Q x K_w^T
        float s0r = 0.f, s1r = 0.f, s2r = 0.f, s3r = 0.f;
#pragma unroll
        for (int kt = 0; kt < 8; kt++) {
            const int k0 = kt * 8;
            uint32_t a0 = Qs[g*KS_STRIDE + k0 + tig];
            uint32_t a1 = Qs[(g+8)*KS_STRIDE + k0 + tig];
            uint32_t a2 = Qs[g*KS_STRIDE + k0 + tig + 4];
            uint32_t a3 = Qs[(g+8)*KS_STRIDE + k0 + tig + 4];
            uint32_t b0 = f2tf(Kst[(r0 + g)*KS_STRIDE + k0 + tig]);
            uint32_t b1 = f2tf(Kst[(r0 + g)*KS_STRIDE + k0 + tig + 4]);
            mma_tf32(s0r, s1r, s2r, s3r, a0, a1, a2, a3, b0, b1);
        }

        // masks
        const int jA = c0 + r0 + 2*tig;
        const int jB = jA + 1;
        const int iA = g, iB = g + 8;
        const bool vA = jA < s1, vB = jB < s1;
        const float pA = vA ? padmask[b*TOTKV + jA] * (-1e9f) : 0.f;
        const float pB = vB ? padmask[b*TOTKV + jB] * (-1e9f) : 0.f;
        s0r = vA ? s0r + pA + ((jA > PASTLEN + iA) ? -1e9f : 0.f) : -1e30f;
        s1r = vB ? s1r + pB + ((jB > PASTLEN + iA) ? -1e9f : 0.f) : -1e30f;
        s2r = vA ? s2r + pA + ((jA > PASTLEN + iB) ? -1e9f : 0.f) : -1e30f;
        s3r = vB ? s3r + pB + ((jB > PASTLEN + iB) ? -1e9f : 0.f) : -1e30f;

        // per-warp online softmax (4-lane row groups)
        float mxA = fmaxf(s0r, s1r);
        float mxB = fmaxf(s2r, s3r);
        mxA = fmaxf(mxA, __shfl_xor_sync(0xffffffffu, mxA, 1));
        mxA = fmaxf(mxA, __shfl_xor_sync(0xffffffffu, mxA, 2));
        mxB = fmaxf(mxB, __shfl_xor_sync(0xffffffffu, mxB, 1));
        mxB = fmaxf(mxB, __shfl_xor_sync(0xffffffffu, mxB, 2));

        const float mn1 = fmaxf(m1, mxA);
        const float mn2 = fmaxf(m2, mxB);
        const float cor1 = __expf(m1 - mn1);
        const float cor2 = __expf(m2 - mn2);
        const float p0 = __expf(s0r - mn1);
        const float p1 = __expf(s1r - mn1);
        const float p2 = __expf(s2r - mn2);
        const float p3 = __expf(s3r - mn2);
        float ls1 = p0 + p1;
        float ls2 = p2 + p3;
        ls1 += __shfl_xor_sync(0xffffffffu, ls1, 1);
        ls1 += __shfl_xor_sync(0xffffffffu, ls1, 2);
        ls2 += __shfl_xor_sync(0xffffffffu, ls2, 1);
        ls2 += __shfl_xor_sync(0xffffffffu, ls2, 2);
        l1 = l1 * cor1 + ls1;  m1 = mn1;
        l2 = l2 * cor2 + ls2;  m2 = mn2;

#pragma unroll
        for (int nt = 0; nt < 8; nt++) {
            acc[nt][0] *= cor1; acc[nt][1] *= cor1;
            acc[nt][2] *= cor2; acc[nt][3] *= cor2;
        }

        // P (C-frag) -> A-frag via shfl, cvt to tf32
        const uint32_t u0 = f2tf(p0), u1 = f2tf(p1), u2 = f2tf(p2), u3 = f2tf(p3);
        const int src0 = (lane & ~3) | (tig >> 1);
        const int src2 = src0 + 2;
        const uint32_t x0 = __shfl_sync(0xffffffffu, u0, src0);
        const uint32_t x1 = __shfl_sync(0xffffffffu, u1, src0);
        const uint32_t y0 = __shfl_sync(0xffffffffu, u0, src2);
        const uint32_t y1 = __shfl_sync(0xffffffffu, u1, src2);
        const uint32_t z0 = __shfl_sync(0xffffffffu, u2, src0);
        const uint32_t z1 = __shfl_sync(0xffffffffu, u2, src2);
        const uint32_t q0 = __shfl_sync(0xffffffffu, u3, src0);
        const uint32_t q1 = __shfl_sync(0xffffffffu, u3, src2);
        const uint32_t pa0 = (tig & 1) ? x1 : x0;
        const uint32_t pa2 = (tig & 1) ? y1 : y0;
        const uint32_t pa1 = (tig & 1) ? q0 : z0;
        const uint32_t pa3 = (tig & 1) ? q1 : z1;

        // PV: acc += P_w x V_w
#pragma unroll
        for (int nt = 0; nt < 8; nt++) {
            const int d0 = nt * 8;
            uint32_t b0 = f2tf(Vst[(r0 + tig)*VS_STRIDE + d0 + g]);
            uint32_t b1 = f2tf(Vst[(r0 + tig + 4)*VS_STRIDE + d0 + g]);
            mma_tf32(acc[nt][0], acc[nt][1], acc[nt][2], acc[nt][3],
                     pa0, pa1, pa2, pa3, b0, b1);
        }
    };

    // ---- prologue: fill the ring ----
#pragma unroll
    for (int ci = 0; ci < STAGES; ci++) issue_chunk(ci);

    const int nchunks = (s1 - s0 + CHUNK2 - 1) / CHUNK2;
    for (int ci = 0; ci < nchunks; ci++) {
        asm volatile("cp.async.wait_group 3;" ::: "memory");   // chunk ci landed
        __syncthreads();
        compute_chunk(s0 + ci*CHUNK2, ci & (STAGES-1));
        __syncthreads();                                       // stage free for reuse
        issue_chunk(ci + STAGES);
    }

    // ================= block-level merge (smem overlay) =================
    asm volatile("cp.async.wait_group 0;" ::: "memory");
    __syncthreads();   // all warps done reading K/V/Q smem

#pragma unroll
    for (int nt = 0; nt < 8; nt++) {
        const int d = nt*8 + 2*tig;
        mrg_acc[(w*QL + g)  *HDIM + d]     = acc[nt][0];
        mrg_acc[(w*QL + g)  *HDIM + d + 1] = acc[nt][1];
        mrg_acc[(w*QL + g+8)*HDIM + d]     = acc[nt][2];
        mrg_acc[(w*QL + g+8)*HDIM + d + 1] = acc[nt][3];
    }
    if (tig == 0) {
        mrg_m[w*QL + g]     = m1;  mrg_m[w*QL + g + 8] = m2;
        mrg_l[w*QL + g]     = l1;  mrg_l[w*QL + g + 8] = l2;
    }
    __syncthreads();

    // thread t -> (q = t>>4, dg = t&15): merge 8 warps, write one float4
    {
        const int q = t >> 4, dg = t & 15;
        float mg = -1e30f;
#pragma unroll
        for (int ww = 0; ww < NWARP; ww++)
            mg = fmaxf(mg, mrg_m[ww*QL + q]);
        float L = 0.f;
        float4 a = make_float4(0.f, 0.f, 0.f, 0.f);
#pragma unroll
        for (int ww = 0; ww < NWARP; ww++) {
            const float wgt = __expf(mrg_m[ww*QL + q] - mg);
            L += mrg_l[ww*QL + q] * wgt;
            const float4 v = *(const float4*)&mrg_acc[(ww*QL + q)*HDIM + dg*4];
            a.x += v.x*wgt; a.y += v.y*wgt; a.z += v.z*wgt; a.w += v.w*wgt;
        }
        const int pb = blockIdx.x;               // bh*NSPLIT + sp
        *(float4*)&g_part_acc[((size_t)pb*QL + q)*HDIM + dg*4] = a;
        if (dg == 0) {
            g_part_m[pb*QL + q] = mg;
            g_part_l[pb*QL + q] = L;
        }
    }
}

// ============================================================
// Kernel 3: combine 16 split partials per bh -> permuted mid layout.
// ============================================================
__global__ __launch_bounds__(256) void combine_kernel()
{
    const int bh = blockIdx.x;
    const int b = bh >> 4, h = bh & 15;
    const int t = threadIdx.x;
    const int i = t >> 4, dg = t & 15;

    float mg = -1e30f;
#pragma unroll
    for (int sp = 0; sp < NSPLIT; sp++)
        mg = fmaxf(mg, g_part_m[(bh*NSPLIT + sp)*QL + i]);

    float L = 0.f;
    float4 acc = make_float4(0.f, 0.f, 0.f, 0.f);
#pragma unroll
    for (int sp = 0; sp < NSPLIT; sp++) {
        const int pi = (bh*NSPLIT + sp)*QL + i;
        const float wgt = __expf(g_part_m[pi] - mg);
        L += g_part_l[pi] * wgt;
        const float4 a = *(const float4*)&g_part_acc[(size_t)pi*HDIM + dg*4];
        acc.x += a.x * wgt; acc.y += a.y * wgt; acc.z += a.z * wgt; acc.w += a.w * wgt;
    }
    const float inv = 1.f / L;
    const float v[4] = {acc.x*inv, acc.y*inv, acc.z*inv, acc.w*inv};
#pragma unroll
    for (int k = 0; k < 4; k++) {
        const int d = dg*4 + k;
        g_mid[b*(QL*HID) + (d >> 2)*HID + (d & 3)*256 + i*16 + h] = v[k];
    }
}

// ============================================================
// Kernel 4a: output projection split-K partial.
// ============================================================
__global__ __launch_bounds__(256) void oproj_part_kernel(
    const float* __restrict__ Wo)
{
    __shared__ float As[64][17];
    __shared__ float Ws[64][17];

    const int tid = threadIdx.x;
    const int tx = tid & 15, ty = tid >> 4;
    const int col0 = blockIdx.x * 64;
    const int row0 = blockIdx.y * 64;
    const int ks   = blockIdx.z;

    float acc[4][4];
#pragma unroll
    for (int r = 0; r < 4; r++)
#pragma unroll
        for (int c = 0; c < 4; c++) acc[r][c] = 0.f;

    const int lr = tid >> 2;
    const int lk = (tid & 3) * 4;
    const float* Arow = g_mid + (size_t)(row0 + lr) * HID + ks*KSLICE + lk;
    const float* Wrow = Wo    + (size_t)(col0 + lr) * HID + ks*KSLICE + lk;

    float4 a4 = *(const float4*)Arow;
    float4 w4 = *(const float4*)Wrow;

    for (int t = 0; t < KSLICE/16; t++) {
        As[lr][lk] = a4.x; As[lr][lk+1] = a4.y; As[lr][lk+2] = a4.z; As[lr][lk+3] = a4.w;
        Ws[lr][lk] = w4.x; Ws[lr][lk+1] = w4.y; Ws[lr][lk+2] = w4.z; Ws[lr][lk+3] = w4.w;
        __syncthreads();
        if (t < KSLICE/16 - 1) {
            a4 = *(const float4*)(Arow + (t+1)*16);
            w4 = *(const float4*)(Wrow + (t+1)*16);
        }
#pragma unroll
        for (int kk = 0; kk < 16; kk++) {
            float av[4], wv[4];
#pragma unroll
            for (int r = 0; r < 4; r++) av[r] = As[ty*4 + r][kk];
#pragma unroll
            for (int c = 0; c < 4; c++) wv[c] = Ws[tx*4 + c][kk];
#pragma unroll
            for (int r = 0; r < 4; r++)
#pragma unroll
                for (int c = 0; c < 4; c++) acc[r][c] += av[r] * wv[c];
        }
        __syncthreads();
    }

#pragma unroll
    for (int r = 0; r < 4; r++) {
        const int m = row0 + ty*4 + r;
        float4 o = make_float4(acc[r][0], acc[r][1], acc[r][2], acc[r][3]);
        *(float4*)&g_op_pp[((size_t)ks*128 + m)*HID + col0 + tx*4] = o;
    }
}

// ============================================================
// Kernel 4b: reduce oproj partials + bias -> out.
// ============================================================
__global__ __launch_bounds__(256) void oproj_reduce_kernel(
    const float* __restrict__ bo, float* __restrict__ out)
{
    const int idx = blockIdx.x * 256 + threadIdx.x;
    const int m = idx >> 8;
    const int n = (idx & 255) * 4;
    const size_t base = (size_t)m*HID + n;

    float4 s = *(const float4*)&g_op_pp[base];
#pragma unroll
    for (int ks = 1; ks < KSPLIT; ks++) {
        float4 p = *(const float4*)&g_op_pp[(size_t)ks*128*HID + base];
        s.x += p.x; s.y += p.y; s.z += p.z; s.w += p.w;
    }
    s.x += bo[n]; s.y += bo[n+1]; s.z += bo[n+2]; s.w += bo[n+3];
    *(float4*)&out[base] = s;
}

// ============================================================
extern "C" void kernel_launch(void* const* d_in, const int* in_sizes, int n_in,
                              void* d_out, int out_size)
{
    const float* hidden  = (const float*)d_in[0];
    const float* past_k  = (const float*)d_in[1];
    const float* past_v  = (const float*)d_in[2];
    // d_in[3] causal_mask: computed analytically (j > PASTLEN + i)
    const float* padmask = (const float*)d_in[4];
    const float* Wq = (const float*)d_in[5];
    const float* bq = (const float*)d_in[6];
    const float* Wk = (const float*)d_in[7];
    const float* bk = (const float*)d_in[8];
    const float* Wv = (const float*)d_in[9];
    const float* bv = (const float*)d_in[10];
    const float* Wo = (const float*)d_in[11];
    const float* bo = (const float*)d_in[12];
    float* out = (float*)d_out;

    cudaFuncSetAttribute(attn_mma_kernel,
                         cudaFuncAttributeMaxDynamicSharedMemorySize, ATTN_SMEM);

    qkv_part_kernel<<<dim3(48, 2, KSPLIT), 256>>>(hidden, Wq, Wk, Wv);
    qkv_reduce_kernel<<<384, 256>>>(bq, bk, bv);
    attn_mma_kernel<<<BB*NHAT*NSPLIT, 256, ATTN_SMEM>>>(past_k, past_v, padmask);
    combine_kernel<<<BB*NHAT, 256>>>();
    oproj_part_kernel<<<dim3(16, 2, KSPLIT), 256>>>(Wo);
    oproj_reduce_kernel<<<128, 256>>>(bo, out);
}

// round 14
// speedup vs baseline: 1.9709x; 1.9484x over previous
#include <cuda_runtime.h>
#include <cuda_bf16.h>
#include <cstdint>

// ---------------- problem constants ----------------
#define BB      8
#define QL      16
#define NHAT    16
#define HDIM    64
#define HID     1024
#define PASTLEN 8192
#define TOTKV   8208            // PASTLEN + QL
#define NSPLIT  16
#define SPLITBASE 512           // 8 chunks of 64; split 15 takes +16 tail
#define CHUNK2  64
#define NWARP   8
#define STAGES  2
#define KSPLIT  4
#define KSLICE  (HID / KSPLIT)  // 256

// attn dynamic smem layout (bytes)
#define QS_BYTES   (QL*68*4)                 // 4352
#define KS_STRIDE  68
#define VS_STRIDE  72
#define KS_STAGE_B (CHUNK2*KS_STRIDE*4)      // 17408
#define VS_STAGE_B (CHUNK2*VS_STRIDE*4)      // 18432
#define KS_BYTES   (STAGES*KS_STAGE_B)       // 34816
#define VS_BYTES   (STAGES*VS_STAGE_B)       // 36864
#define ATTN_SMEM  (QS_BYTES + KS_BYTES + VS_BYTES)   // 76032 -> 2 CTAs/SM

// ---------------- device scratch (no allocation allowed) ----------------
__device__ float g_q  [BB*NHAT*QL*HDIM];                    // pre-scaled by 0.125
__device__ float g_k  [BB*NHAT*QL*HDIM];                    // new K rows
__device__ float g_v  [BB*NHAT*QL*HDIM];                    // new V rows
__device__ float g_qkv_pp[KSPLIT*128*3072];                 // qkv split-K partials
__device__ float g_op_pp [KSPLIT*128*HID];                  // oproj split-K partials
__device__ float g_part_acc[BB*NHAT*NSPLIT*QL*HDIM];        // per-split PV partials
__device__ float g_part_m  [BB*NHAT*NSPLIT*QL];
__device__ float g_part_l  [BB*NHAT*NSPLIT*QL];
__device__ float g_mid [BB*QL*HID];                         // permuted attn output

// ---------------- helpers ----------------
__device__ __forceinline__ uint32_t f2tf(float f) {
    uint32_t u;
    asm("cvt.rna.tf32.f32 %0, %1;" : "=r"(u) : "f"(f));
    return u;
}
__device__ __forceinline__ void mma_tf32(float& c0, float& c1, float& c2, float& c3,
    uint32_t a0, uint32_t a1, uint32_t a2, uint32_t a3, uint32_t b0, uint32_t b1)
{
    asm("mma.sync.aligned.m16n8k8.row.col.f32.tf32.tf32.f32 "
        "{%0,%1,%2,%3}, {%4,%5,%6,%7}, {%8,%9}, {%0,%1,%2,%3};"
        : "+f"(c0), "+f"(c1), "+f"(c2), "+f"(c3)
        : "r"(a0), "r"(a1), "r"(a2), "r"(a3), "r"(b0), "r"(b1));
}
__device__ __forceinline__ uint32_t smem_u32(const void* p) {
    uint32_t a;
    asm("{ .reg .u64 t; cvta.to.shared.u64 t, %1; cvt.u32.u64 %0, t; }"
        : "=r"(a) : "l"(p));
    return a;
}
__device__ __forceinline__ void cp_async16(uint32_t dst, const void* src) {
    asm volatile("cp.async.cg.shared.global [%0], [%1], 16;" :: "r"(dst), "l"(src));
}
__device__ __forceinline__ void cp_commit() {
    asm volatile("cp.async.commit_group;" ::: "memory");
}

// ============================================================
// Kernel 1a: fused QKV projection, split-K partial.
// ============================================================
__global__ __launch_bounds__(256) void qkv_part_kernel(
    const float* __restrict__ A,
    const float* __restrict__ Wq, const float* __restrict__ Wk,
    const float* __restrict__ Wv)
{
    __shared__ float As[64][17];
    __shared__ float Ws[64][17];

    const int tid = threadIdx.x;
    const int tx = tid & 15, ty = tid >> 4;
    const int col0 = blockIdx.x * 64;
    const int row0 = blockIdx.y * 64;
    const int ks   = blockIdx.z;
    const int mat  = col0 >> 10;
    const int f0   = col0 & 1023;
    const float* W = (mat == 0) ? Wq : (mat == 1) ? Wk : Wv;

    float acc[4][4];
#pragma unroll
    for (int r = 0; r < 4; r++)
#pragma unroll
        for (int c = 0; c < 4; c++) acc[r][c] = 0.f;

    const int lr = tid >> 2;
    const int lk = (tid & 3) * 4;
    const float* Arow = A + (size_t)(row0 + lr) * HID + ks*KSLICE + lk;
    const float* Wrow = W + (size_t)(f0  + lr) * HID + ks*KSLICE + lk;

    float4 a4 = *(const float4*)Arow;
    float4 w4 = *(const float4*)Wrow;

    for (int t = 0; t < KSLICE/16; t++) {
        As[lr][lk] = a4.x; As[lr][lk+1] = a4.y; As[lr][lk+2] = a4.z; As[lr][lk+3] = a4.w;
        Ws[lr][lk] = w4.x; Ws[lr][lk+1] = w4.y; Ws[lr][lk+2] = w4.z; Ws[lr][lk+3] = w4.w;
        __syncthreads();
        if (t < KSLICE/16 - 1) {
            a4 = *(const float4*)(Arow + (t+1)*16);
            w4 = *(const float4*)(Wrow + (t+1)*16);
        }
#pragma unroll
        for (int kk = 0; kk < 16; kk++) {
            float av[4], wv[4];
#pragma unroll
            for (int r = 0; r < 4; r++) av[r] = As[ty*4 + r][kk];
#pragma unroll
            for (int c = 0; c < 4; c++) wv[c] = Ws[tx*4 + c][kk];
#pragma unroll
            for (int r = 0; r < 4; r++)
#pragma unroll
                for (int c = 0; c < 4; c++) acc[r][c] += av[r] * wv[c];
        }
        __syncthreads();
    }

#pragma unroll
    for (int r = 0; r < 4; r++) {
        const int m = row0 + ty*4 + r;
        float4 o = make_float4(acc[r][0], acc[r][1], acc[r][2], acc[r][3]);
        *(float4*)&g_qkv_pp[((size_t)ks*128 + m)*3072 + col0 + tx*4] = o;
    }
}

// ============================================================
// Kernel 1b: reduce qkv split-K partials + bias -> [b][h][i][d]
// ============================================================
__global__ __launch_bounds__(256) void qkv_reduce_kernel(
    const float* __restrict__ bq, const float* __restrict__ bk,
    const float* __restrict__ bv)
{
    const int idx = blockIdx.x * 256 + threadIdx.x;
    const int m = idx / 768;
    const int f = (idx - m*768) * 4;
    const size_t base = (size_t)m*3072 + f;

    float4 s = *(const float4*)&g_qkv_pp[base];
#pragma unroll
    for (int ks = 1; ks < KSPLIT; ks++) {
        float4 p = *(const float4*)&g_qkv_pp[(size_t)ks*128*3072 + base];
        s.x += p.x; s.y += p.y; s.z += p.z; s.w += p.w;
    }

    const int mat = f >> 10;
    const int fl  = f & 1023;
    const float* bias = (mat == 0) ? bq : (mat == 1) ? bk : bv;
    s.x += bias[fl]; s.y += bias[fl+1]; s.z += bias[fl+2]; s.w += bias[fl+3];

    const int b = m >> 4, iq = m & 15;
    const int h = fl >> 6, d = fl & 63;
    const int dst = ((b*NHAT + h)*QL + iq)*HDIM + d;
    if (mat == 0) {
        s.x *= 0.125f; s.y *= 0.125f; s.z *= 0.125f; s.w *= 0.125f;
        *(float4*)&g_q[dst] = s;
    } else if (mat == 1) {
        *(float4*)&g_k[dst] = s;
    } else {
        *(float4*)&g_v[dst] = s;
    }
}

// ============================================================
// Kernel 2: flash attention, tf32 MMA, 2-stage cp.async ring,
// 2 CTAs/SM, block-level partial merge.
// grid = BB*NHAT*NSPLIT, block = 256.
// ============================================================
__global__ __launch_bounds__(256, 2) void attn_mma_kernel(
    const float* __restrict__ past_k,
    const float* __restrict__ past_v,
    const float* __restrict__ padmask)
{
    extern __shared__ __align__(16) char dynsm[];
    uint32_t* Qs  = (uint32_t*)dynsm;                       // [16][68] tf32
    float*    KsB = (float*)(dynsm + QS_BYTES);             // [2][64][68] fp32
    float*    VsB = (float*)(dynsm + QS_BYTES + KS_BYTES);  // [2][64][72] fp32
    // epilogue overlay (into Ks region, after final sync)
    float* mrg_acc = (float*)(dynsm + QS_BYTES);            // [8][16][64] = 32KB
    float* mrg_m   = mrg_acc + NWARP*QL*HDIM;               // [8][16]
    float* mrg_l   = mrg_m + NWARP*QL;

    const int t    = threadIdx.x;
    const int lane = t & 31;
    const int w    = t >> 5;
    const int bh   = blockIdx.x >> 4;
    const int sp   = blockIdx.x & (NSPLIT - 1);
    const int b    = bh >> 4;
    const int s0   = sp * SPLITBASE;
    const int s1   = (sp == NSPLIT-1) ? TOTKV : s0 + SPLITBASE;

    const float4* pk4 = (const float4*)past_k;
    const float4* pv4 = (const float4*)past_v;
    const float4* gk4 = (const float4*)g_k;
    const float4* gv4 = (const float4*)g_v;

    // ---- stage Q (tf32) ----
    {
        float4 q4 = ((const float4*)g_q)[bh*256 + t];
        const int row = t >> 4, c = (t & 15) * 4;
        Qs[row*KS_STRIDE + c]   = f2tf(q4.x);
        Qs[row*KS_STRIDE + c+1] = f2tf(q4.y);
        Qs[row*KS_STRIDE + c+2] = f2tf(q4.z);
        Qs[row*KS_STRIDE + c+3] = f2tf(q4.w);
    }

    const int g   = lane >> 2;     // query row base
    const int tig = lane & 3;      // thread-in-group
    const int r0  = w * 8;         // this warp's kv-row base within chunk
    const int ldrow = t >> 4, ldc = t & 15;   // cooperative-load ids

    const uint32_t ks_sm = smem_u32(KsB);
    const uint32_t vs_sm = smem_u32(VsB);

    float m1 = -1e30f, m2 = -1e30f, l1 = 0.f, l2 = 0.f;
    float acc[8][4];
#pragma unroll
    for (int nt = 0; nt < 8; nt++)
#pragma unroll
        for (int c = 0; c < 4; c++) acc[nt][c] = 0.f;

    // ---- issue cp.async for one chunk into its ring stage ----
    auto issue_chunk = [&](int ci) {
        const int base = s0 + ci*CHUNK2;
        if (base < s1) {
            const int stage = ci & (STAGES-1);
            const int nrows = min(CHUNK2, s1 - base);
            const uint32_t kst = ks_sm + stage*KS_STAGE_B + ldc*16;
            const uint32_t vst = vs_sm + stage*VS_STAGE_B + ldc*16;
#pragma unroll
            for (int it = 0; it < 4; it++) {
                const int row = ldrow + it*16;
                if (row < nrows) {
                    const int gr = base + row;
                    const float4 *ksrc, *vsrc;
                    if (gr < PASTLEN) {
                        ksrc = pk4 + (size_t)(bh*PASTLEN + gr)*16 + ldc;
                        vsrc = pv4 + (size_t)(bh*PASTLEN + gr)*16 + ldc;
                    } else {
                        ksrc = gk4 + (size_t)(bh*QL + (gr - PASTLEN))*16 + ldc;
                        vsrc = gv4 + (size_t)(bh*QL + (gr - PASTLEN))*16 + ldc;
                    }
                    cp_async16(kst + row*(KS_STRIDE*4), ksrc);
                    cp_async16(vst + row*(VS_STRIDE*4), vsrc);
                }
            }
        }
        cp_commit();   // always commit (possibly empty) to keep group count uniform
    };

    // ---- per-chunk compute (reads stage buffers; cvt to tf32 at use) ----
    auto compute_chunk = [&](int c0, int stage) {
        const float* Kst = KsB + stage*(CHUNK2*KS_STRIDE);
        const float* Vst = VsB + stage*(CHUNK2*VS_STRIDE);

        // scores: S_w(16q x 8kv) = Q x K_w^T
        float s0r = 0.f, s1r = 0.f, s2r = 0.f, s3r = 0.f;
#pragma unroll
        for (int kt = 0; kt < 8; kt++) {
            const int k0 = kt * 8;
            uint32_t a0 = Qs[g*KS_STRIDE + k0 + tig];
            uint32_t a1 = Qs[(g+8)*KS_STRIDE + k0 + tig];
            uint32_t a2 = Qs[g*KS_STRIDE + k0 + tig + 4];
            uint32_t a3 = Qs[(g+8)*KS_STRIDE + k0 + tig + 4];
            uint32_t b0 = f2tf(Kst[(r0 + g)*KS_STRIDE + k0 + tig]);
            uint32_t b1 = f2tf(Kst[(r0 + g)*KS_STRIDE + k0 + tig + 4]);
            mma_tf32(s0r, s1r, s2r, s3r, a0, a1, a2, a3, b0, b1);
        }

        // masks
        const int jA = c0 + r0 + 2*tig;
        const int jB = jA + 1;
        const int iA = g, iB = g + 8;
        const bool vA = jA < s1, vB = jB < s1;
        const float pA = vA ? padmask[b*TOTKV + jA] * (-1e9f) : 0.f;
        const float pB = vB ? padmask[b*TOTKV + jB] * (-1e9f) : 0.f;
        s0r = vA ? s0r + pA + ((jA > PASTLEN + iA) ? -1e9f : 0.f) : -1e30f;
        s1r = vB ? s1r + pB + ((jB > PASTLEN + iA) ? -1e9f : 0.f) : -1e30f;
        s2r = vA ? s2r + pA + ((jA > PASTLEN + iB) ? -1e9f : 0.f) : -1e30f;
        s3r = vB ? s3r + pB + ((jB > PASTLEN + iB) ? -1e9f : 0.f) : -1e30f;

        // per-warp online softmax (4-lane row groups)
        float mxA = fmaxf(s0r, s1r);
        float mxB = fmaxf(s2r, s3r);
        mxA = fmaxf(mxA, __shfl_xor_sync(0xffffffffu, mxA, 1));
        mxA = fmaxf(mxA, __shfl_xor_sync(0xffffffffu, mxA, 2));
        mxB = fmaxf(mxB, __shfl_xor_sync(0xffffffffu, mxB, 1));
        mxB = fmaxf(mxB, __shfl_xor_sync(0xffffffffu, mxB, 2));

        const float mn1 = fmaxf(m1, mxA);
        const float mn2 = fmaxf(m2, mxB);
        const float cor1 = __expf(m1 - mn1);
        const float cor2 = __expf(m2 - mn2);
        const float p0 = __expf(s0r - mn1);
        const float p1 = __expf(s1r - mn1);
        const float p2 = __expf(s2r - mn2);
        const float p3 = __expf(s3r - mn2);
        float ls1 = p0 + p1;
        float ls2 = p2 + p3;
        ls1 += __shfl_xor_sync(0xffffffffu, ls1, 1);
        ls1 += __shfl_xor_sync(0xffffffffu, ls1, 2);
        ls2 += __shfl_xor_sync(0xffffffffu, ls2, 1);
        ls2 += __shfl_xor_sync(0xffffffffu, ls2, 2);
        l1 = l1 * cor1 + ls1;  m1 = mn1;
        l2 = l2 * cor2 + ls2;  m2 = mn2;

#pragma unroll
        for (int nt = 0; nt < 8; nt++) {
            acc[nt][0] *= cor1; acc[nt][1] *= cor1;
            acc[nt][2] *= cor2; acc[nt][3] *= cor2;
        }

        // P (C-frag) -> A-frag via shfl, cvt to tf32
        const uint32_t u0 = f2tf(p0), u1 = f2tf(p1), u2 = f2tf(p2), u3 = f2tf(p3);
        const int src0 = (lane & ~3) | (tig >> 1);
        const int src2 = src0 + 2;
        const uint32_t x0 = __shfl_sync(0xffffffffu, u0, src0);
        const uint32_t x1 = __shfl_sync(0xffffffffu, u1, src0);
        const uint32_t y0 = __shfl_sync(0xffffffffu, u0, src2);
        const uint32_t y1 = __shfl_sync(0xffffffffu, u1, src2);
        const uint32_t z0 = __shfl_sync(0xffffffffu, u2, src0);
        const uint32_t z1 = __shfl_sync(0xffffffffu, u2, src2);
        const uint32_t q0 = __shfl_sync(0xffffffffu, u3, src0);
        const uint32_t q1 = __shfl_sync(0xffffffffu, u3, src2);
        const uint32_t pa0 = (tig & 1) ? x1 : x0;
        const uint32_t pa2 = (tig & 1) ? y1 : y0;
        const uint32_t pa1 = (tig & 1) ? q0 : z0;
        const uint32_t pa3 = (tig & 1) ? q1 : z1;

        // PV: acc += P_w x V_w
#pragma unroll
        for (int nt = 0; nt < 8; nt++) {
            const int d0 = nt * 8;
            uint32_t b0 = f2tf(Vst[(r0 + tig)*VS_STRIDE + d0 + g]);
            uint32_t b1 = f2tf(Vst[(r0 + tig + 4)*VS_STRIDE + d0 + g]);
            mma_tf32(acc[nt][0], acc[nt][1], acc[nt][2], acc[nt][3],
                     pa0, pa1, pa2, pa3, b0, b1);
        }
    };

    // ---- prologue: fill the 2-stage ring ----
    issue_chunk(0);
    issue_chunk(1);

    const int nchunks = (s1 - s0 + CHUNK2 - 1) / CHUNK2;
    for (int ci = 0; ci < nchunks; ci++) {
        asm volatile("cp.async.wait_group 1;" ::: "memory");   // chunk ci landed
        __syncthreads();
        compute_chunk(s0 + ci*CHUNK2, ci & (STAGES-1));
        __syncthreads();                                       // stage free for reuse
        issue_chunk(ci + STAGES);
    }

    // ================= block-level merge (smem overlay) =================
    asm volatile("cp.async.wait_group 0;" ::: "memory");
    __syncthreads();   // all warps done reading K/V/Q smem

#pragma unroll
    for (int nt = 0; nt < 8; nt++) {
        const int d = nt*8 + 2*tig;
        mrg_acc[(w*QL + g)  *HDIM + d]     = acc[nt][0];
        mrg_acc[(w*QL + g)  *HDIM + d + 1] = acc[nt][1];
        mrg_acc[(w*QL + g+8)*HDIM + d]     = acc[nt][2];
        mrg_acc[(w*QL + g+8)*HDIM + d + 1] = acc[nt][3];
    }
    if (tig == 0) {
        mrg_m[w*QL + g]     = m1;  mrg_m[w*QL + g + 8] = m2;
        mrg_l[w*QL + g]     = l1;  mrg_l[w*QL + g + 8] = l2;
    }
    __syncthreads();

    // thread t -> (q = t>>4, dg = t&15): merge 8 warps, write one float4
    {
        const int q = t >> 4, dg = t & 15;
        float mg = -1e30f;
#pragma unroll
        for (int ww = 0; ww < NWARP; ww++)
            mg = fmaxf(mg, mrg_m[ww*QL + q]);
        float L = 0.f;
        float4 a = make_float4(0.f, 0.f, 0.f, 0.f);
#pragma unroll
        for (int ww = 0; ww < NWARP; ww++) {
            const float wgt = __expf(mrg_m[ww*QL + q] - mg);
            L += mrg_l[ww*QL + q] * wgt;
            const float4 v = *(const float4*)&mrg_acc[(ww*QL + q)*HDIM + dg*4];
            a.x += v.x*wgt; a.y += v.y*wgt; a.z += v.z*wgt; a.w += v.w*wgt;
        }
        const int pb = blockIdx.x;               // bh*NSPLIT + sp
        *(float4*)&g_part_acc[((size_t)pb*QL + q)*HDIM + dg*4] = a;
        if (dg == 0) {
            g_part_m[pb*QL + q] = mg;
            g_part_l[pb*QL + q] = L;
        }
    }
}

// ============================================================
// Kernel 3: combine 16 split partials per bh -> permuted mid layout.
// ============================================================
__global__ __launch_bounds__(256) void combine_kernel()
{
    const int bh = blockIdx.x;
    const int b = bh >> 4, h = bh & 15;
    const int t = threadIdx.x;
    const int i = t >> 4, dg = t & 15;

    float mg = -1e30f;
#pragma unroll
    for (int sp = 0; sp < NSPLIT; sp++)
        mg = fmaxf(mg, g_part_m[(bh*NSPLIT + sp)*QL + i]);

    float L = 0.f;
    float4 acc = make_float4(0.f, 0.f, 0.f, 0.f);
#pragma unroll
    for (int sp = 0; sp < NSPLIT; sp++) {
        const int pi = (bh*NSPLIT + sp)*QL + i;
        const float wgt = __expf(g_part_m[pi] - mg);
        L += g_part_l[pi] * wgt;
        const float4 a = *(const float4*)&g_part_acc[(size_t)pi*HDIM + dg*4];
        acc.x += a.x * wgt; acc.y += a.y * wgt; acc.z += a.z * wgt; acc.w += a.w * wgt;
    }
    const float inv = 1.f / L;
    const float v[4] = {acc.x*inv, acc.y*inv, acc.z*inv, acc.w*inv};
#pragma unroll
    for (int k = 0; k < 4; k++) {
        const int d = dg*4 + k;
        g_mid[b*(QL*HID) + (d >> 2)*HID + (d & 3)*256 + i*16 + h] = v[k];
    }
}

// ============================================================
// Kernel 4a: output projection split-K partial.
// ============================================================
__global__ __launch_bounds__(256) void oproj_part_kernel(
    const float* __restrict__ Wo)
{
    __shared__ float As[64][17];
    __shared__ float Ws[64][17];

    const int tid = threadIdx.x;
    const int tx = tid & 15, ty = tid >> 4;
    const int col0 = blockIdx.x * 64;
    const int row0 = blockIdx.y * 64;
    const int ks   = blockIdx.z;

    float acc[4][4];
#pragma unroll
    for (int r = 0; r < 4; r++)
#pragma unroll
        for (int c = 0; c < 4; c++) acc[r][c] = 0.f;

    const int lr = tid >> 2;
    const int lk = (tid & 3) * 4;
    const float* Arow = g_mid + (size_t)(row0 + lr) * HID + ks*KSLICE + lk;
    const float* Wrow = Wo    + (size_t)(col0 + lr) * HID + ks*KSLICE + lk;

    float4 a4 = *(const float4*)Arow;
    float4 w4 = *(const float4*)Wrow;

    for (int t = 0; t < KSLICE/16; t++) {
        As[lr][lk] = a4.x; As[lr][lk+1] = a4.y; As[lr][lk+2] = a4.z; As[lr][lk+3] = a4.w;
        Ws[lr][lk] = w4.x; Ws[lr][lk+1] = w4.y; Ws[lr][lk+2] = w4.z; Ws[lr][lk+3] = w4.w;
        __syncthreads();
        if (t < KSLICE/16 - 1) {
            a4 = *(const float4*)(Arow + (t+1)*16);
            w4 = *(const float4*)(Wrow + (t+1)*16);
        }
#pragma unroll
        for (int kk = 0; kk < 16; kk++) {
            float av[4], wv[4];
#pragma unroll
            for (int r = 0; r < 4; r++) av[r] = As[ty*4 + r][kk];
#pragma unroll
            for (int c = 0; c < 4; c++) wv[c] = Ws[tx*4 + c][kk];
#pragma unroll
            for (int r = 0; r < 4; r++)
#pragma unroll
                for (int c = 0; c < 4; c++) acc[r][c] += av[r] * wv[c];
        }
        __syncthreads();
    }

#pragma unroll
    for (int r = 0; r < 4; r++) {
        const int m = row0 + ty*4 + r;
        float4 o = make_float4(acc[r][0], acc[r][1], acc[r][2], acc[r][3]);
        *(float4*)&g_op_pp[((size_t)ks*128 + m)*HID + col0 + tx*4] = o;
    }
}

// ============================================================
// Kernel 4b: reduce oproj partials + bias -> out.
// ============================================================
__global__ __launch_bounds__(256) void oproj_reduce_kernel(
    const float* __restrict__ bo, float* __restrict__ out)
{
    const int idx = blockIdx.x * 256 + threadIdx.x;
    const int m = idx >> 8;
    const int n = (idx & 255) * 4;
    const size_t base = (size_t)m*HID + n;

    float4 s = *(const float4*)&g_op_pp[base];
#pragma unroll
    for (int ks = 1; ks < KSPLIT; ks++) {
        float4 p = *(const float4*)&g_op_pp[(size_t)ks*128*HID + base];
        s.x += p.x; s.y += p.y; s.z += p.z; s.w += p.w;
    }
    s.x += bo[n]; s.y += bo[n+1]; s.z += bo[n+2]; s.w += bo[n+3];
    *(float4*)&out[base] = s;
}

// ============================================================
extern "C" void kernel_launch(void* const* d_in, const int* in_sizes, int n_in,
                              void* d_out, int out_size)
{
    const float* hidden  = (const float*)d_in[0];
    const float* past_k  = (const float*)d_in[1];
    const float* past_v  = (const float*)d_in[2];
    // d_in[3] causal_mask: computed analytically (j > PASTLEN + i)
    const float* padmask = (const float*)d_in[4];
    const float* Wq = (const float*)d_in[5];
    const float* bq = (const float*)d_in[6];
    const float* Wk = (const float*)d_in[7];
    const float* bk = (const float*)d_in[8];
    const float* Wv = (const float*)d_in[9];
    const float* bv = (const float*)d_in[10];
    const float* Wo = (const float*)d_in[11];
    const float* bo = (const float*)d_in[12];
    float* out = (float*)d_out;

    cudaFuncSetAttribute(attn_mma_kernel,
                         cudaFuncAttributeMaxDynamicSharedMemorySize, ATTN_SMEM);

    qkv_part_kernel<<<dim3(48, 2, KSPLIT), 256>>>(hidden, Wq, Wk, Wv);
    qkv_reduce_kernel<<<384, 256>>>(bq, bk, bv);
    attn_mma_kernel<<<BB*NHAT*NSPLIT, 256, ATTN_SMEM>>>(past_k, past_v, padmask);
    combine_kernel<<<BB*NHAT, 256>>>();
    oproj_part_kernel<<<dim3(16, 2, KSPLIT), 256>>>(Wo);
    oproj_reduce_kernel<<<128, 256>>>(bo, out);
}

// round 15
// speedup vs baseline: 1.9780x; 1.0036x over previous
#include <cuda_runtime.h>
#include <cuda_bf16.h>
#include <cstdint>

// ---------------- problem constants ----------------
#define BB      8
#define QL      16
#define NHAT    16
#define HDIM    64
#define HID     1024
#define PASTLEN 8192
#define TOTKV   8208            // PASTLEN + QL
#define NSPLIT  16
#define SPLITBASE 512           // 8 chunks of 64; split 15 takes +16 tail
#define CHUNK2  64
#define NWARP   8
#define STAGES  3
#define KSPLIT  4
#define KSLICE  (HID / KSPLIT)  // 256

// attn dynamic smem layout (bytes)
#define QS_BYTES   (QL*68*4)                 // 4352
#define KS_STRIDE  68
#define VS_STRIDE  72
#define KS_STAGE_B (CHUNK2*KS_STRIDE*4)      // 17408
#define VS_STAGE_B (CHUNK2*VS_STRIDE*4)      // 18432
#define KS_BYTES   (STAGES*KS_STAGE_B)       // 52224
#define VS_BYTES   (STAGES*VS_STAGE_B)       // 55296
#define ATTN_SMEM  (QS_BYTES + KS_BYTES + VS_BYTES)   // 111872 -> 2 CTAs/SM

// ---------------- device scratch (no allocation allowed) ----------------
__device__ float g_q  [BB*NHAT*QL*HDIM];                    // pre-scaled by 0.125
__device__ float g_k  [BB*NHAT*QL*HDIM];                    // new K rows
__device__ float g_v  [BB*NHAT*QL*HDIM];                    // new V rows
__device__ float g_qkv_pp[KSPLIT*128*3072];                 // qkv split-K partials
__device__ float g_op_pp [KSPLIT*128*HID];                  // oproj split-K partials
__device__ float g_part_acc[BB*NHAT*NSPLIT*QL*HDIM];        // per-split PV partials
__device__ float g_part_m  [BB*NHAT*NSPLIT*QL];
__device__ float g_part_l  [BB*NHAT*NSPLIT*QL];
__device__ float g_mid [BB*QL*HID];                         // permuted attn output

// ---------------- helpers ----------------
__device__ __forceinline__ uint32_t f2tf(float f) {
    uint32_t u;
    asm("cvt.rna.tf32.f32 %0, %1;" : "=r"(u) : "f"(f));
    return u;
}
__device__ __forceinline__ void mma_tf32(float& c0, float& c1, float& c2, float& c3,
    uint32_t a0, uint32_t a1, uint32_t a2, uint32_t a3, uint32_t b0, uint32_t b1)
{
    asm("mma.sync.aligned.m16n8k8.row.col.f32.tf32.tf32.f32 "
        "{%0,%1,%2,%3}, {%4,%5,%6,%7}, {%8,%9}, {%0,%1,%2,%3};"
        : "+f"(c0), "+f"(c1), "+f"(c2), "+f"(c3)
        : "r"(a0), "r"(a1), "r"(a2), "r"(a3), "r"(b0), "r"(b1));
}
__device__ __forceinline__ uint32_t smem_u32(const void* p) {
    uint32_t a;
    asm("{ .reg .u64 t; cvta.to.shared.u64 t, %1; cvt.u32.u64 %0, t; }"
        : "=r"(a) : "l"(p));
    return a;
}
__device__ __forceinline__ void cp_async16(uint32_t dst, const void* src) {
    asm volatile("cp.async.cg.shared.global [%0], [%1], 16;" :: "r"(dst), "l"(src));
}
__device__ __forceinline__ void cp_commit() {
    asm volatile("cp.async.commit_group;" ::: "memory");
}

// ============================================================
// Kernel 1a: fused QKV projection, split-K partial.
// ============================================================
__global__ __launch_bounds__(256) void qkv_part_kernel(
    const float* __restrict__ A,
    const float* __restrict__ Wq, const float* __restrict__ Wk,
    const float* __restrict__ Wv)
{
    __shared__ float As[64][17];
    __shared__ float Ws[64][17];

    const int tid = threadIdx.x;
    const int tx = tid & 15, ty = tid >> 4;
    const int col0 = blockIdx.x * 64;
    const int row0 = blockIdx.y * 64;
    const int ks   = blockIdx.z;
    const int mat  = col0 >> 10;
    const int f0   = col0 & 1023;
    const float* W = (mat == 0) ? Wq : (mat == 1) ? Wk : Wv;

    float acc[4][4];
#pragma unroll
    for (int r = 0; r < 4; r++)
#pragma unroll
        for (int c = 0; c < 4; c++) acc[r][c] = 0.f;

    const int lr = tid >> 2;
    const int lk = (tid & 3) * 4;
    const float* Arow = A + (size_t)(row0 + lr) * HID + ks*KSLICE + lk;
    const float* Wrow = W + (size_t)(f0  + lr) * HID + ks*KSLICE + lk;

    float4 a4 = *(const float4*)Arow;
    float4 w4 = *(const float4*)Wrow;

    for (int t = 0; t < KSLICE/16; t++) {
        As[lr][lk] = a4.x; As[lr][lk+1] = a4.y; As[lr][lk+2] = a4.z; As[lr][lk+3] = a4.w;
        Ws[lr][lk] = w4.x; Ws[lr][lk+1] = w4.y; Ws[lr][lk+2] = w4.z; Ws[lr][lk+3] = w4.w;
        __syncthreads();
        if (t < KSLICE/16 - 1) {
            a4 = *(const float4*)(Arow + (t+1)*16);
            w4 = *(const float4*)(Wrow + (t+1)*16);
        }
#pragma unroll
        for (int kk = 0; kk < 16; kk++) {
            float av[4], wv[4];
#pragma unroll
            for (int r = 0; r < 4; r++) av[r] = As[ty*4 + r][kk];
#pragma unroll
            for (int c = 0; c < 4; c++) wv[c] = Ws[tx*4 + c][kk];
#pragma unroll
            for (int r = 0; r < 4; r++)
#pragma unroll
                for (int c = 0; c < 4; c++) acc[r][c] += av[r] * wv[c];
        }
        __syncthreads();
    }

#pragma unroll
    for (int r = 0; r < 4; r++) {
        const int m = row0 + ty*4 + r;
        float4 o = make_float4(acc[r][0], acc[r][1], acc[r][2], acc[r][3]);
        *(float4*)&g_qkv_pp[((size_t)ks*128 + m)*3072 + col0 + tx*4] = o;
    }
}

// ============================================================
// Kernel 1b: reduce qkv split-K partials + bias -> [b][h][i][d]
// ============================================================
__global__ __launch_bounds__(256) void qkv_reduce_kernel(
    const float* __restrict__ bq, const float* __restrict__ bk,
    const float* __restrict__ bv)
{
    const int idx = blockIdx.x * 256 + threadIdx.x;
    const int m = idx / 768;
    const int f = (idx - m*768) * 4;
    const size_t base = (size_t)m*3072 + f;

    float4 s = *(const float4*)&g_qkv_pp[base];
#pragma unroll
    for (int ks = 1; ks < KSPLIT; ks++) {
        float4 p = *(const float4*)&g_qkv_pp[(size_t)ks*128*3072 + base];
        s.x += p.x; s.y += p.y; s.z += p.z; s.w += p.w;
    }

    const int mat = f >> 10;
    const int fl  = f & 1023;
    const float* bias = (mat == 0) ? bq : (mat == 1) ? bk : bv;
    s.x += bias[fl]; s.y += bias[fl+1]; s.z += bias[fl+2]; s.w += bias[fl+3];

    const int b = m >> 4, iq = m & 15;
    const int h = fl >> 6, d = fl & 63;
    const int dst = ((b*NHAT + h)*QL + iq)*HDIM + d;
    if (mat == 0) {
        s.x *= 0.125f; s.y *= 0.125f; s.z *= 0.125f; s.w *= 0.125f;
        *(float4*)&g_q[dst] = s;
    } else if (mat == 1) {
        *(float4*)&g_k[dst] = s;
    } else {
        *(float4*)&g_v[dst] = s;
    }
}

// ============================================================
// Kernel 2: flash attention, tf32 MMA, 3-stage cp.async ring,
// single barrier per chunk, 2 CTAs/SM, block-level partial merge.
// grid = BB*NHAT*NSPLIT, block = 256.
// ============================================================
__global__ __launch_bounds__(256, 2) void attn_mma_kernel(
    const float* __restrict__ past_k,
    const float* __restrict__ past_v,
    const float* __restrict__ padmask)
{
    extern __shared__ __align__(16) char dynsm[];
    uint32_t* Qs  = (uint32_t*)dynsm;                       // [16][68] tf32
    float*    KsB = (float*)(dynsm + QS_BYTES);             // [3][64][68] fp32
    float*    VsB = (float*)(dynsm + QS_BYTES + KS_BYTES);  // [3][64][72] fp32
    // epilogue overlay (into Ks region, after final sync)
    float* mrg_acc = (float*)(dynsm + QS_BYTES);            // [8][16][64] = 32KB
    float* mrg_m   = mrg_acc + NWARP*QL*HDIM;               // [8][16]
    float* mrg_l   = mrg_m + NWARP*QL;

    const int t    = threadIdx.x;
    const int lane = t & 31;
    const int w    = t >> 5;
    const int bh   = blockIdx.x >> 4;
    const int sp   = blockIdx.x & (NSPLIT - 1);
    const int b    = bh >> 4;
    const int s0   = sp * SPLITBASE;
    const int s1   = (sp == NSPLIT-1) ? TOTKV : s0 + SPLITBASE;

    const float4* pk4 = (const float4*)past_k;
    const float4* pv4 = (const float4*)past_v;
    const float4* gk4 = (const float4*)g_k;
    const float4* gv4 = (const float4*)g_v;

    // ---- stage Q (tf32) ----
    {
        float4 q4 = ((const float4*)g_q)[bh*256 + t];
        const int row = t >> 4, c = (t & 15) * 4;
        Qs[row*KS_STRIDE + c]   = f2tf(q4.x);
        Qs[row*KS_STRIDE + c+1] = f2tf(q4.y);
        Qs[row*KS_STRIDE + c+2] = f2tf(q4.z);
        Qs[row*KS_STRIDE + c+3] = f2tf(q4.w);
    }

    const int g   = lane >> 2;     // query row base
    const int tig = lane & 3;      // thread-in-group
    const int r0  = w * 8;         // this warp's kv-row base within chunk
    const int ldrow = t >> 4, ldc = t & 15;   // cooperative-load ids

    const uint32_t ks_sm = smem_u32(KsB);
    const uint32_t vs_sm = smem_u32(VsB);

    float m1 = -1e30f, m2 = -1e30f, l1 = 0.f, l2 = 0.f;
    float acc[8][4];
#pragma unroll
    for (int nt = 0; nt < 8; nt++)
#pragma unroll
        for (int c = 0; c < 4; c++) acc[nt][c] = 0.f;

    // ---- issue cp.async for one chunk into its ring stage ----
    auto issue_chunk = [&](int ci) {
        const int base = s0 + ci*CHUNK2;
        if (base < s1) {
            const int stage = ci % STAGES;
            const int nrows = min(CHUNK2, s1 - base);
            const uint32_t kst = ks_sm + stage*KS_STAGE_B + ldc*16;
            const uint32_t vst = vs_sm + stage*VS_STAGE_B + ldc*16;
#pragma unroll
            for (int it = 0; it < 4; it++) {
                const int row = ldrow + it*16;
                if (row < nrows) {
                    const int gr = base + row;
                    const float4 *ksrc, *vsrc;
                    if (gr < PASTLEN) {
                        ksrc = pk4 + (size_t)(bh*PASTLEN + gr)*16 + ldc;
                        vsrc = pv4 + (size_t)(bh*PASTLEN + gr)*16 + ldc;
                    } else {
                        ksrc = gk4 + (size_t)(bh*QL + (gr - PASTLEN))*16 + ldc;
                        vsrc = gv4 + (size_t)(bh*QL + (gr - PASTLEN))*16 + ldc;
                    }
                    cp_async16(kst + row*(KS_STRIDE*4), ksrc);
                    cp_async16(vst + row*(VS_STRIDE*4), vsrc);
                }
            }
        }
        cp_commit();   // always commit (possibly empty) to keep group count uniform
    };

    // ---- per-chunk compute (reads stage buffers; cvt to tf32 at use) ----
    auto compute_chunk = [&](int c0, int stage) {
        const float* Kst = KsB + stage*(CHUNK2*KS_STRIDE);
        const float* Vst = VsB + stage*(CHUNK2*VS_STRIDE);

        // scores: S_w(16q x 8kv) = Q x K_w^T
        float s0r = 0.f, s1r = 0.f, s2r = 0.f, s3r = 0.f;
#pragma unroll
        for (int kt = 0; kt < 8; kt++) {
            const int k0 = kt * 8;
            uint32_t a0 = Qs[g*KS_STRIDE + k0 + tig];
            uint32_t a1 = Qs[(g+8)*KS_STRIDE + k0 + tig];
            uint32_t a2 = Qs[g*KS_STRIDE + k0 + tig + 4];
            uint32_t a3 = Qs[(g+8)*KS_STRIDE + k0 + tig + 4];
            uint32_t b0 = f2tf(Kst[(r0 + g)*KS_STRIDE + k0 + tig]);
            uint32_t b1 = f2tf(Kst[(r0 + g)*KS_STRIDE + k0 + tig + 4]);
            mma_tf32(s0r, s1r, s2r, s3r, a0, a1, a2, a3, b0, b1);
        }

        // masks
        const int jA = c0 + r0 + 2*tig;
        const int jB = jA + 1;
        const int iA = g, iB = g + 8;
        const bool vA = jA < s1, vB = jB < s1;
        const float pA = vA ? padmask[b*TOTKV + jA] * (-1e9f) : 0.f;
        const float pB = vB ? padmask[b*TOTKV + jB] * (-1e9f) : 0.f;
        s0r = vA ? s0r + pA + ((jA > PASTLEN + iA) ? -1e9f : 0.f) : -1e30f;
        s1r = vB ? s1r + pB + ((jB > PASTLEN + iA) ? -1e9f : 0.f) : -1e30f;
        s2r = vA ? s2r + pA + ((jA > PASTLEN + iB) ? -1e9f : 0.f) : -1e30f;
        s3r = vB ? s3r + pB + ((jB > PASTLEN + iB) ? -1e9f : 0.f) : -1e30f;

        // per-warp online softmax (4-lane row groups)
        float mxA = fmaxf(s0r, s1r);
        float mxB = fmaxf(s2r, s3r);
        mxA = fmaxf(mxA, __shfl_xor_sync(0xffffffffu, mxA, 1));
        mxA = fmaxf(mxA, __shfl_xor_sync(0xffffffffu, mxA, 2));
        mxB = fmaxf(mxB, __shfl_xor_sync(0xffffffffu, mxB, 1));
        mxB = fmaxf(mxB, __shfl_xor_sync(0xffffffffu, mxB, 2));

        const float mn1 = fmaxf(m1, mxA);
        const float mn2 = fmaxf(m2, mxB);
        const float cor1 = __expf(m1 - mn1);
        const float cor2 = __expf(m2 - mn2);
        const float p0 = __expf(s0r - mn1);
        const float p1 = __expf(s1r - mn1);
        const float p2 = __expf(s2r - mn2);
        const float p3 = __expf(s3r - mn2);
        float ls1 = p0 + p1;
        float ls2 = p2 + p3;
        ls1 += __shfl_xor_sync(0xffffffffu, ls1, 1);
        ls1 += __shfl_xor_sync(0xffffffffu, ls1, 2);
        ls2 += __shfl_xor_sync(0xffffffffu, ls2, 1);
        ls2 += __shfl_xor_sync(0xffffffffu, ls2, 2);
        l1 = l1 * cor1 + ls1;  m1 = mn1;
        l2 = l2 * cor2 + ls2;  m2 = mn2;

#pragma unroll
        for (int nt = 0; nt < 8; nt++) {
            acc[nt][0] *= cor1; acc[nt][1] *= cor1;
            acc[nt][2] *= cor2; acc[nt][3] *= cor2;
        }

        // P (C-frag) -> A-frag via shfl, cvt to tf32
        const uint32_t u0 = f2tf(p0), u1 = f2tf(p1), u2 = f2tf(p2), u3 = f2tf(p3);
        const int src0 = (lane & ~3) | (tig >> 1);
        const int src2 = src0 + 2;
        const uint32_t x0 = __shfl_sync(0xffffffffu, u0, src0);
        const uint32_t x1 = __shfl_sync(0xffffffffu, u1, src0);
        const uint32_t y0 = __shfl_sync(0xffffffffu, u0, src2);
        const uint32_t y1 = __shfl_sync(0xffffffffu, u1, src2);
        const uint32_t z0 = __shfl_sync(0xffffffffu, u2, src0);
        const uint32_t z1 = __shfl_sync(0xffffffffu, u2, src2);
        const uint32_t q0 = __shfl_sync(0xffffffffu, u3, src0);
        const uint32_t q1 = __shfl_sync(0xffffffffu, u3, src2);
        const uint32_t pa0 = (tig & 1) ? x1 : x0;
        const uint32_t pa2 = (tig & 1) ? y1 : y0;
        const uint32_t pa1 = (tig & 1) ? q0 : z0;
        const uint32_t pa3 = (tig & 1) ? q1 : z1;

        // PV: acc += P_w x V_w
#pragma unroll
        for (int nt = 0; nt < 8; nt++) {
            const int d0 = nt * 8;
            uint32_t b0 = f2tf(Vst[(r0 + tig)*VS_STRIDE + d0 + g]);
            uint32_t b1 = f2tf(Vst[(r0 + tig + 4)*VS_STRIDE + d0 + g]);
            mma_tf32(acc[nt][0], acc[nt][1], acc[nt][2], acc[nt][3],
                     pa0, pa1, pa2, pa3, b0, b1);
        }
    };

    // ---- prologue: issue first two chunks ----
    issue_chunk(0);
    issue_chunk(1);

    // ---- mainloop: ONE barrier per chunk.
    // At iter ci: wait(chunk ci landed); sync (proves compute(ci-1) done
    // in all warps -> stage (ci-1)%3 free); issue chunk ci+2 into that
    // stage; compute chunk ci from stage ci%3.
    const int nchunks = (s1 - s0 + CHUNK2 - 1) / CHUNK2;
    for (int ci = 0; ci < nchunks; ci++) {
        asm volatile("cp.async.wait_group 1;" ::: "memory");   // chunk ci landed
        __syncthreads();
        issue_chunk(ci + 2);
        compute_chunk(s0 + ci*CHUNK2, ci % STAGES);
    }

    // ================= block-level merge (smem overlay) =================
    asm volatile("cp.async.wait_group 0;" ::: "memory");
    __syncthreads();   // all warps done reading K/V/Q smem

#pragma unroll
    for (int nt = 0; nt < 8; nt++) {
        const int d = nt*8 + 2*tig;
        mrg_acc[(w*QL + g)  *HDIM + d]     = acc[nt][0];
        mrg_acc[(w*QL + g)  *HDIM + d + 1] = acc[nt][1];
        mrg_acc[(w*QL + g+8)*HDIM + d]     = acc[nt][2];
        mrg_acc[(w*QL + g+8)*HDIM + d + 1] = acc[nt][3];
    }
    if (tig == 0) {
        mrg_m[w*QL + g]     = m1;  mrg_m[w*QL + g + 8] = m2;
        mrg_l[w*QL + g]     = l1;  mrg_l[w*QL + g + 8] = l2;
    }
    __syncthreads();

    // thread t -> (q = t>>4, dg = t&15): merge 8 warps, write one float4
    {
        const int q = t >> 4, dg = t & 15;
        float mg = -1e30f;
#pragma unroll
        for (int ww = 0; ww < NWARP; ww++)
            mg = fmaxf(mg, mrg_m[ww*QL + q]);
        float L = 0.f;
        float4 a = make_float4(0.f, 0.f, 0.f, 0.f);
#pragma unroll
        for (int ww = 0; ww < NWARP; ww++) {
            const float wgt = __expf(mrg_m[ww*QL + q] - mg);
            L += mrg_l[ww*QL + q] * wgt;
            const float4 v = *(const float4*)&mrg_acc[(ww*QL + q)*HDIM + dg*4];
            a.x += v.x*wgt; a.y += v.y*wgt; a.z += v.z*wgt; a.w += v.w*wgt;
        }
        const int pb = blockIdx.x;               // bh*NSPLIT + sp
        *(float4*)&g_part_acc[((size_t)pb*QL + q)*HDIM + dg*4] = a;
        if (dg == 0) {
            g_part_m[pb*QL + q] = mg;
            g_part_l[pb*QL + q] = L;
        }
    }
}

// ============================================================
// Kernel 3: combine 16 split partials per bh -> permuted mid layout.
// ============================================================
__global__ __launch_bounds__(256) void combine_kernel()
{
    const int bh = blockIdx.x;
    const int b = bh >> 4, h = bh & 15;
    const int t = threadIdx.x;
    const int i = t >> 4, dg = t & 15;

    float mg = -1e30f;
#pragma unroll
    for (int sp = 0; sp < NSPLIT; sp++)
        mg = fmaxf(mg, g_part_m[(bh*NSPLIT + sp)*QL + i]);

    float L = 0.f;
    float4 acc = make_float4(0.f, 0.f, 0.f, 0.f);
#pragma unroll
    for (int sp = 0; sp < NSPLIT; sp++) {
        const int pi = (bh*NSPLIT + sp)*QL + i;
        const float wgt = __expf(g_part_m[pi] - mg);
        L += g_part_l[pi] * wgt;
        const float4 a = *(const float4*)&g_part_acc[(size_t)pi*HDIM + dg*4];
        acc.x += a.x * wgt; acc.y += a.y * wgt; acc.z += a.z * wgt; acc.w += a.w * wgt;
    }
    const float inv = 1.f / L;
    const float v[4] = {acc.x*inv, acc.y*inv, acc.z*inv, acc.w*inv};
#pragma unroll
    for (int k = 0; k < 4; k++) {
        const int d = dg*4 + k;
        g_mid[b*(QL*HID) + (d >> 2)*HID + (d & 3)*256 + i*16 + h] = v[k];
    }
}

// ============================================================
// Kernel 4a: output projection split-K partial.
// ============================================================
__global__ __launch_bounds__(256) void oproj_part_kernel(
    const float* __restrict__ Wo)
{
    __shared__ float As[64][17];
    __shared__ float Ws[64][17];

    const int tid = threadIdx.x;
    const int tx = tid & 15, ty = tid >> 4;
    const int col0 = blockIdx.x * 64;
    const int row0 = blockIdx.y * 64;
    const int ks   = blockIdx.z;

    float acc[4][4];
#pragma unroll
    for (int r = 0; r < 4; r++)
#pragma unroll
        for (int c = 0; c < 4; c++) acc[r][c] = 0.f;

    const int lr = tid >> 2;
    const int lk = (tid & 3) * 4;
    const float* Arow = g_mid + (size_t)(row0 + lr) * HID + ks*KSLICE + lk;
    const float* Wrow = Wo    + (size_t)(col0 + lr) * HID + ks*KSLICE + lk;

    float4 a4 = *(const float4*)Arow;
    float4 w4 = *(const float4*)Wrow;

    for (int t = 0; t < KSLICE/16; t++) {
        As[lr][lk] = a4.x; As[lr][lk+1] = a4.y; As[lr][lk+2] = a4.z; As[lr][lk+3] = a4.w;
        Ws[lr][lk] = w4.x; Ws[lr][lk+1] = w4.y; Ws[lr][lk+2] = w4.z; Ws[lr][lk+3] = w4.w;
        __syncthreads();
        if (t < KSLICE/16 - 1) {
            a4 = *(const float4*)(Arow + (t+1)*16);
            w4 = *(const float4*)(Wrow + (t+1)*16);
        }
#pragma unroll
        for (int kk = 0; kk < 16; kk++) {
            float av[4], wv[4];
#pragma unroll
            for (int r = 0; r < 4; r++) av[r] = As[ty*4 + r][kk];
#pragma unroll
            for (int c = 0; c < 4; c++) wv[c] = Ws[tx*4 + c][kk];
#pragma unroll
            for (int r = 0; r < 4; r++)
#pragma unroll
                for (int c = 0; c < 4; c++) acc[r][c] += av[r] * wv[c];
        }
        __syncthreads();
    }

#pragma unroll
    for (int r = 0; r < 4; r++) {
        const int m = row0 + ty*4 + r;
        float4 o = make_float4(acc[r][0], acc[r][1], acc[r][2], acc[r][3]);
        *(float4*)&g_op_pp[((size_t)ks*128 + m)*HID + col0 + tx*4] = o;
    }
}

// ============================================================
// Kernel 4b: reduce oproj partials + bias -> out.
// ============================================================
__global__ __launch_bounds__(256) void oproj_reduce_kernel(
    const float* __restrict__ bo, float* __restrict__ out)
{
    const int idx = blockIdx.x * 256 + threadIdx.x;
    const int m = idx >> 8;
    const int n = (idx & 255) * 4;
    const size_t base = (size_t)m*HID + n;

    float4 s = *(const float4*)&g_op_pp[base];
#pragma unroll
    for (int ks = 1; ks < KSPLIT; ks++) {
        float4 p = *(const float4*)&g_op_pp[(size_t)ks*128*HID + base];
        s.x += p.x; s.y += p.y; s.z += p.z; s.w += p.w;
    }
    s.x += bo[n]; s.y += bo[n+1]; s.z += bo[n+2]; s.w += bo[n+3];
    *(float4*)&out[base] = s;
}

// ============================================================
extern "C" void kernel_launch(void* const* d_in, const int* in_sizes, int n_in,
                              void* d_out, int out_size)
{
    const float* hidden  = (const float*)d_in[0];
    const float* past_k  = (const float*)d_in[1];
    const float* past_v  = (const float*)d_in[2];
    // d_in[3] causal_mask: computed analytically (j > PASTLEN + i)
    const float* padmask = (const float*)d_in[4];
    const float* Wq = (const float*)d_in[5];
    const float* bq = (const float*)d_in[6];
    const float* Wk = (const float*)d_in[7];
    const float* bk = (const float*)d_in[8];
    const float* Wv = (const float*)d_in[9];
    const float* bv = (const float*)d_in[10];
    const float* Wo = (const float*)d_in[11];
    const float* bo = (const float*)d_in[12];
    float* out = (float*)d_out;

    cudaFuncSetAttribute(attn_mma_kernel,
                         cudaFuncAttributeMaxDynamicSharedMemorySize, ATTN_SMEM);

    qkv_part_kernel<<<dim3(48, 2, KSPLIT), 256>>>(hidden, Wq, Wk, Wv);
    qkv_reduce_kernel<<<384, 256>>>(bq, bk, bv);
    attn_mma_kernel<<<BB*NHAT*NSPLIT, 256, ATTN_SMEM>>>(past_k, past_v, padmask);
    combine_kernel<<<BB*NHAT, 256>>>();
    oproj_part_kernel<<<dim3(16, 2, KSPLIT), 256>>>(Wo);
    oproj_reduce_kernel<<<128, 256>>>(bo, out);
}

// round 17
// speedup vs baseline: 1.9937x; 1.0080x over previous
#include <cuda_runtime.h>
#include <cuda_bf16.h>
#include <cstdint>

// ---------------- problem constants ----------------
#define BB      8
#define QL      16
#define NHAT    16
#define HDIM    64
#define HID     1024
#define PASTLEN 8192
#define TOTKV   8208            // PASTLEN + QL
#define NSPLIT  16
#define SPLITBASE 512           // 8 chunks of 64; split 15 takes +16 tail
#define CHUNK2  64
#define NWARP   8
#define STAGES  3
#define KSPLIT  4
#define KSLICE  (HID / KSPLIT)  // 256

// attn dynamic smem layout (bytes)
#define QS_BYTES   (QL*68*4)                 // 4352
#define KS_STRIDE  68
#define VS_STRIDE  72
#define KS_STAGE_B (CHUNK2*KS_STRIDE*4)      // 17408
#define VS_STAGE_B (CHUNK2*VS_STRIDE*4)      // 18432
#define KS_BYTES   (STAGES*KS_STAGE_B)       // 52224
#define VS_BYTES   (STAGES*VS_STAGE_B)       // 55296
#define ATTN_SMEM  (QS_BYTES + KS_BYTES + VS_BYTES)   // 111872 -> 2 CTAs/SM

// ---------------- device scratch (no allocation allowed) ----------------
__device__ float g_q  [BB*NHAT*QL*HDIM];                    // pre-scaled by 0.125
__device__ float g_k  [BB*NHAT*QL*HDIM];                    // new K rows
__device__ float g_v  [BB*NHAT*QL*HDIM];                    // new V rows
__device__ float g_qkv_pp[KSPLIT*128*3072];                 // qkv split-K partials
__device__ float g_op_pp [KSPLIT*128*HID];                  // oproj split-K partials
__device__ float g_part_acc[BB*NHAT*NSPLIT*QL*HDIM];        // per-split PV partials
__device__ float g_part_m  [BB*NHAT*NSPLIT*QL];
__device__ float g_part_l  [BB*NHAT*NSPLIT*QL];
__device__ float g_mid [BB*QL*HID];                         // permuted attn output

// ---------------- helpers ----------------
__device__ __forceinline__ uint32_t f2tf(float f) {
    uint32_t u;
    asm("cvt.rna.tf32.f32 %0, %1;" : "=r"(u) : "f"(f));
    return u;
}
__device__ __forceinline__ void mma_tf32(float& c0, float& c1, float& c2, float& c3,
    uint32_t a0, uint32_t a1, uint32_t a2, uint32_t a3, uint32_t b0, uint32_t b1)
{
    asm("mma.sync.aligned.m16n8k8.row.col.f32.tf32.tf32.f32 "
        "{%0,%1,%2,%3}, {%4,%5,%6,%7}, {%8,%9}, {%0,%1,%2,%3};"
        : "+f"(c0), "+f"(c1), "+f"(c2), "+f"(c3)
        : "r"(a0), "r"(a1), "r"(a2), "r"(a3), "r"(b0), "r"(b1));
}
__device__ __forceinline__ uint32_t smem_u32(const void* p) {
    uint32_t a;
    asm("{ .reg .u64 t; cvta.to.shared.u64 t, %1; cvt.u32.u64 %0, t; }"
        : "=r"(a) : "l"(p));
    return a;
}
__device__ __forceinline__ void cp_async16(uint32_t dst, const void* src) {
    asm volatile("cp.async.cg.shared.global [%0], [%1], 16;" :: "r"(dst), "l"(src));
}
__device__ __forceinline__ void cp_commit() {
    asm volatile("cp.async.commit_group;" ::: "memory");
}

// ============================================================
// Kernel 1a: fused QKV projection, split-K partial.
// ============================================================
__global__ __launch_bounds__(256) void qkv_part_kernel(
    const float* __restrict__ A,
    const float* __restrict__ Wq, const float* __restrict__ Wk,
    const float* __restrict__ Wv)
{
    __shared__ float As[64][17];
    __shared__ float Ws[64][17];

    const int tid = threadIdx.x;
    const int tx = tid & 15, ty = tid >> 4;
    const int col0 = blockIdx.x * 64;
    const int row0 = blockIdx.y * 64;
    const int ks   = blockIdx.z;
    const int mat  = col0 >> 10;
    const int f0   = col0 & 1023;
    const float* W = (mat == 0) ? Wq : (mat == 1) ? Wk : Wv;

    float acc[4][4];
#pragma unroll
    for (int r = 0; r < 4; r++)
#pragma unroll
        for (int c = 0; c < 4; c++) acc[r][c] = 0.f;

    const int lr = tid >> 2;
    const int lk = (tid & 3) * 4;
    const float* Arow = A + (size_t)(row0 + lr) * HID + ks*KSLICE + lk;
    const float* Wrow = W + (size_t)(f0  + lr) * HID + ks*KSLICE + lk;

    float4 a4 = *(const float4*)Arow;
    float4 w4 = *(const float4*)Wrow;

    for (int t = 0; t < KSLICE/16; t++) {
        As[lr][lk] = a4.x; As[lr][lk+1] = a4.y; As[lr][lk+2] = a4.z; As[lr][lk+3] = a4.w;
        Ws[lr][lk] = w4.x; Ws[lr][lk+1] = w4.y; Ws[lr][lk+2] = w4.z; Ws[lr][lk+3] = w4.w;
        __syncthreads();
        if (t < KSLICE/16 - 1) {
            a4 = *(const float4*)(Arow + (t+1)*16);
            w4 = *(const float4*)(Wrow + (t+1)*16);
        }
#pragma unroll
        for (int kk = 0; kk < 16; kk++) {
            float av[4], wv[4];
#pragma unroll
            for (int r = 0; r < 4; r++) av[r] = As[ty*4 + r][kk];
#pragma unroll
            for (int c = 0; c < 4; c++) wv[c] = Ws[tx*4 + c][kk];
#pragma unroll
            for (int r = 0; r < 4; r++)
#pragma unroll
                for (int c = 0; c < 4; c++) acc[r][c] += av[r] * wv[c];
        }
        __syncthreads();
    }

#pragma unroll
    for (int r = 0; r < 4; r++) {
        const int m = row0 + ty*4 + r;
        float4 o = make_float4(acc[r][0], acc[r][1], acc[r][2], acc[r][3]);
        *(float4*)&g_qkv_pp[((size_t)ks*128 + m)*3072 + col0 + tx*4] = o;
    }
}

// ============================================================
// Kernel 1b: reduce qkv split-K partials + bias -> [b][h][i][d]
// ============================================================
__global__ __launch_bounds__(256) void qkv_reduce_kernel(
    const float* __restrict__ bq, const float* __restrict__ bk,
    const float* __restrict__ bv)
{
    const int idx = blockIdx.x * 256 + threadIdx.x;
    const int m = idx / 768;
    const int f = (idx - m*768) * 4;
    const size_t base = (size_t)m*3072 + f;

    float4 s = *(const float4*)&g_qkv_pp[base];
#pragma unroll
    for (int ks = 1; ks < KSPLIT; ks++) {
        float4 p = *(const float4*)&g_qkv_pp[(size_t)ks*128*3072 + base];
        s.x += p.x; s.y += p.y; s.z += p.z; s.w += p.w;
    }

    const int mat = f >> 10;
    const int fl  = f & 1023;
    const float* bias = (mat == 0) ? bq : (mat == 1) ? bk : bv;
    s.x += bias[fl]; s.y += bias[fl+1]; s.z += bias[fl+2]; s.w += bias[fl+3];

    const int b = m >> 4, iq = m & 15;
    const int h = fl >> 6, d = fl & 63;
    const int dst = ((b*NHAT + h)*QL + iq)*HDIM + d;
    if (mat == 0) {
        s.x *= 0.125f; s.y *= 0.125f; s.z *= 0.125f; s.w *= 0.125f;
        *(float4*)&g_q[dst] = s;
    } else if (mat == 1) {
        *(float4*)&g_k[dst] = s;
    } else {
        *(float4*)&g_v[dst] = s;
    }
}

// ============================================================
// Kernel 2: flash attention, tf32 MMA, 3-stage cp.async ring,
// depth-2 pipeline (prologue 3, wait_group 2, issue after compute),
// 2 CTAs/SM, block-level partial merge.
// grid = BB*NHAT*NSPLIT, block = 256.
// ============================================================
__global__ __launch_bounds__(256, 2) void attn_mma_kernel(
    const float* __restrict__ past_k,
    const float* __restrict__ past_v,
    const float* __restrict__ padmask)
{
    extern __shared__ __align__(16) char dynsm[];
    uint32_t* Qs  = (uint32_t*)dynsm;                       // [16][68] tf32
    float*    KsB = (float*)(dynsm + QS_BYTES);             // [3][64][68] fp32
    float*    VsB = (float*)(dynsm + QS_BYTES + KS_BYTES);  // [3][64][72] fp32
    // epilogue overlay (into Ks region, after final sync)
    float* mrg_acc = (float*)(dynsm + QS_BYTES);            // [8][16][64] = 32KB
    float* mrg_m   = mrg_acc + NWARP*QL*HDIM;               // [8][16]
    float* mrg_l   = mrg_m + NWARP*QL;

    const int t    = threadIdx.x;
    const int lane = t & 31;
    const int w    = t >> 5;
    const int bh   = blockIdx.x >> 4;
    const int sp   = blockIdx.x & (NSPLIT - 1);
    const int b    = bh >> 4;
    const int s0   = sp * SPLITBASE;
    const int s1   = (sp == NSPLIT-1) ? TOTKV : s0 + SPLITBASE;

    const float4* pk4 = (const float4*)past_k;
    const float4* pv4 = (const float4*)past_v;
    const float4* gk4 = (const float4*)g_k;
    const float4* gv4 = (const float4*)g_v;

    // ---- stage Q (tf32) ----
    {
        float4 q4 = ((const float4*)g_q)[bh*256 + t];
        const int row = t >> 4, c = (t & 15) * 4;
        Qs[row*KS_STRIDE + c]   = f2tf(q4.x);
        Qs[row*KS_STRIDE + c+1] = f2tf(q4.y);
        Qs[row*KS_STRIDE + c+2] = f2tf(q4.z);
        Qs[row*KS_STRIDE + c+3] = f2tf(q4.w);
    }

    const int g   = lane >> 2;     // query row base
    const int tig = lane & 3;      // thread-in-group
    const int r0  = w * 8;         // this warp's kv-row base within chunk
    const int ldrow = t >> 4, ldc = t & 15;   // cooperative-load ids

    const uint32_t ks_sm = smem_u32(KsB);
    const uint32_t vs_sm = smem_u32(VsB);

    float m1 = -1e30f, m2 = -1e30f, l1 = 0.f, l2 = 0.f;
    float acc[8][4];
#pragma unroll
    for (int nt = 0; nt < 8; nt++)
#pragma unroll
        for (int c = 0; c < 4; c++) acc[nt][c] = 0.f;

    // ---- issue cp.async for one chunk into its ring stage ----
    auto issue_chunk = [&](int ci) {
        const int base = s0 + ci*CHUNK2;
        if (base < s1) {
            const int stage = ci % STAGES;
            const int nrows = min(CHUNK2, s1 - base);
            const uint32_t kst = ks_sm + stage*KS_STAGE_B + ldc*16;
            const uint32_t vst = vs_sm + stage*VS_STAGE_B + ldc*16;
#pragma unroll
            for (int it = 0; it < 4; it++) {
                const int row = ldrow + it*16;
                if (row < nrows) {
                    const int gr = base + row;
                    const float4 *ksrc, *vsrc;
                    if (gr < PASTLEN) {
                        ksrc = pk4 + (size_t)(bh*PASTLEN + gr)*16 + ldc;
                        vsrc = pv4 + (size_t)(bh*PASTLEN + gr)*16 + ldc;
                    } else {
                        ksrc = gk4 + (size_t)(bh*QL + (gr - PASTLEN))*16 + ldc;
                        vsrc = gv4 + (size_t)(bh*QL + (gr - PASTLEN))*16 + ldc;
                    }
                    cp_async16(kst + row*(KS_STRIDE*4), ksrc);
                    cp_async16(vst + row*(VS_STRIDE*4), vsrc);
                }
            }
        }
        cp_commit();   // always commit (possibly empty) to keep group count uniform
    };

    // ---- per-chunk compute (reads stage buffers; cvt to tf32 at use) ----
    auto compute_chunk = [&](int c0, int stage) {
        const float* Kst = KsB + stage*(CHUNK2*KS_STRIDE);
        const float* Vst = VsB + stage*(CHUNK2*VS_STRIDE);

        // scores: S_w(16q x 8kv) = Q x K_w^T
        float s0r = 0.f, s1r = 0.f, s2r = 0.f, s3r = 0.f;
#pragma unroll
        for (int kt = 0; kt < 8; kt++) {
            const int k0 = kt * 8;
            uint32_t a0 = Qs[g*KS_STRIDE + k0 + tig];
            uint32_t a1 = Qs[(g+8)*KS_STRIDE + k0 + tig];
            uint32_t a2 = Qs[g*KS_STRIDE + k0 + tig + 4];
            uint32_t a3 = Qs[(g+8)*KS_STRIDE + k0 + tig + 4];
            uint32_t b0 = f2tf(Kst[(r0 + g)*KS_STRIDE + k0 + tig]);
            uint32_t b1 = f2tf(Kst[(r0 + g)*KS_STRIDE + k0 + tig + 4]);
            mma_tf32(s0r, s1r, s2r, s3r, a0, a1, a2, a3, b0, b1);
        }

        // masks
        const int jA = c0 + r0 + 2*tig;
        const int jB = jA + 1;
        const int iA = g, iB = g + 8;
        const bool vA = jA < s1, vB = jB < s1;
        const float pA = vA ? padmask[b*TOTKV + jA] * (-1e9f) : 0.f;
        const float pB = vB ? padmask[b*TOTKV + jB] * (-1e9f) : 0.f;
        s0r = vA ? s0r + pA + ((jA > PASTLEN + iA) ? -1e9f : 0.f) : -1e30f;
        s1r = vB ? s1r + pB + ((jB > PASTLEN + iA) ? -1e9f : 0.f) : -1e30f;
        s2r = vA ? s2r + pA + ((jA > PASTLEN + iB) ? -1e9f : 0.f) : -1e30f;
        s3r = vB ? s3r + pB + ((jB > PASTLEN + iB) ? -1e9f : 0.f) : -1e30f;

        // per-warp online softmax (4-lane row groups)
        float mxA = fmaxf(s0r, s1r);
        float mxB = fmaxf(s2r, s3r);
        mxA = fmaxf(mxA, __shfl_xor_sync(0xffffffffu, mxA, 1));
        mxA = fmaxf(mxA, __shfl_xor_sync(0xffffffffu, mxA, 2));
        mxB = fmaxf(mxB, __shfl_xor_sync(0xffffffffu, mxB, 1));
        mxB = fmaxf(mxB, __shfl_xor_sync(0xffffffffu, mxB, 2));

        const float mn1 = fmaxf(m1, mxA);
        const float mn2 = fmaxf(m2, mxB);
        const float cor1 = __expf(m1 - mn1);
        const float cor2 = __expf(m2 - mn2);
        const float p0 = __expf(s0r - mn1);
        const float p1 = __expf(s1r - mn1);
        const float p2 = __expf(s2r - mn2);
        const float p3 = __expf(s3r - mn2);
        float ls1 = p0 + p1;
        float ls2 = p2 + p3;
        ls1 += __shfl_xor_sync(0xffffffffu, ls1, 1);
        ls1 += __shfl_xor_sync(0xffffffffu, ls1, 2);
        ls2 += __shfl_xor_sync(0xffffffffu, ls2, 1);
        ls2 += __shfl_xor_sync(0xffffffffu, ls2, 2);
        l1 = l1 * cor1 + ls1;  m1 = mn1;
        l2 = l2 * cor2 + ls2;  m2 = mn2;

#pragma unroll
        for (int nt = 0; nt < 8; nt++) {
            acc[nt][0] *= cor1; acc[nt][1] *= cor1;
            acc[nt][2] *= cor2; acc[nt][3] *= cor2;
        }

        // P (C-frag) -> A-frag via shfl, cvt to tf32
        const uint32_t u0 = f2tf(p0), u1 = f2tf(p1), u2 = f2tf(p2), u3 = f2tf(p3);
        const int src0 = (lane & ~3) | (tig >> 1);
        const int src2 = src0 + 2;
        const uint32_t x0 = __shfl_sync(0xffffffffu, u0, src0);
        const uint32_t x1 = __shfl_sync(0xffffffffu, u1, src0);
        const uint32_t y0 = __shfl_sync(0xffffffffu, u0, src2);
        const uint32_t y1 = __shfl_sync(0xffffffffu, u1, src2);
        const uint32_t z0 = __shfl_sync(0xffffffffu, u2, src0);
        const uint32_t z1 = __shfl_sync(0xffffffffu, u2, src2);
        const uint32_t q0 = __shfl_sync(0xffffffffu, u3, src0);
        const uint32_t q1 = __shfl_sync(0xffffffffu, u3, src2);
        const uint32_t pa0 = (tig & 1) ? x1 : x0;
        const uint32_t pa2 = (tig & 1) ? y1 : y0;
        const uint32_t pa1 = (tig & 1) ? q0 : z0;
        const uint32_t pa3 = (tig & 1) ? q1 : z1;

        // PV: acc += P_w x V_w
#pragma unroll
        for (int nt = 0; nt < 8; nt++) {
            const int d0 = nt * 8;
            uint32_t b0 = f2tf(Vst[(r0 + tig)*VS_STRIDE + d0 + g]);
            uint32_t b1 = f2tf(Vst[(r0 + tig + 4)*VS_STRIDE + d0 + g]);
            mma_tf32(acc[nt][0], acc[nt][1], acc[nt][2], acc[nt][3],
                     pa0, pa1, pa2, pa3, b0, b1);
        }
    };

    // ---- prologue: fill all 3 stages (groups 0,1,2) ----
    issue_chunk(0);
    issue_chunk(1);
    issue_chunk(2);

    // ---- mainloop, depth-2 coverage.
    // At iter ci entry: committed groups 0..ci+2. wait_group 2 -> pending
    // {ci+1, ci+2}; group ci (chunk ci) COMPLETE. sync makes all threads'
    // copies visible. compute(ci) reads stage ci%3 (in-flight writes hit
    // (ci+1)%3 and (ci+2)%3 -- disjoint). sync proves all warps done
    // reading stage ci%3, then issue chunk ci+3 into that stage.
    const int nchunks = (s1 - s0 + CHUNK2 - 1) / CHUNK2;
    for (int ci = 0; ci < nchunks; ci++) {
        asm volatile("cp.async.wait_group 2;" ::: "memory");   // chunk ci landed
        __syncthreads();
        compute_chunk(s0 + ci*CHUNK2, ci % STAGES);
        __syncthreads();
        issue_chunk(ci + 3);
    }

    // ================= block-level merge (smem overlay) =================
    asm volatile("cp.async.wait_group 0;" ::: "memory");
    __syncthreads();   // all warps done reading K/V/Q smem

#pragma unroll
    for (int nt = 0; nt < 8; nt++) {
        const int d = nt*8 + 2*tig;
        mrg_acc[(w*QL + g)  *HDIM + d]     = acc[nt][0];
        mrg_acc[(w*QL + g)  *HDIM + d + 1] = acc[nt][1];
        mrg_acc[(w*QL + g+8)*HDIM + d]     = acc[nt][2];
        mrg_acc[(w*QL + g+8)*HDIM + d + 1] = acc[nt][3];
    }
    if (tig == 0) {
        mrg_m[w*QL + g]     = m1;  mrg_m[w*QL + g + 8] = m2;
        mrg_l[w*QL + g]     = l1;  mrg_l[w*QL + g + 8] = l2;
    }
    __syncthreads();

    // thread t -> (q = t>>4, dg = t&15): merge 8 warps, write one float4
    {
        const int q = t >> 4, dg = t & 15;
        float mg = -1e30f;
#pragma unroll
        for (int ww = 0; ww < NWARP; ww++)
            mg = fmaxf(mg, mrg_m[ww*QL + q]);
        float L = 0.f;
        float4 a = make_float4(0.f, 0.f, 0.f, 0.f);
#pragma unroll
        for (int ww = 0; ww < NWARP; ww++) {
            const float wgt = __expf(mrg_m[ww*QL + q] - mg);
            L += mrg_l[ww*QL + q] * wgt;
            const float4 v = *(const float4*)&mrg_acc[(ww*QL + q)*HDIM + dg*4];
            a.x += v.x*wgt; a.y += v.y*wgt; a.z += v.z*wgt; a.w += v.w*wgt;
        }
        const int pb = blockIdx.x;               // bh*NSPLIT + sp
        *(float4*)&g_part_acc[((size_t)pb*QL + q)*HDIM + dg*4] = a;
        if (dg == 0) {
            g_part_m[pb*QL + q] = mg;
            g_part_l[pb*QL + q] = L;
        }
    }
}

// ============================================================
// Kernel 3: combine 16 split partials per bh -> permuted mid layout.
// ============================================================
__global__ __launch_bounds__(256) void combine_kernel()
{
    const int bh = blockIdx.x;
    const int b = bh >> 4, h = bh & 15;
    const int t = threadIdx.x;
    const int i = t >> 4, dg = t & 15;

    float mg = -1e30f;
#pragma unroll
    for (int sp = 0; sp < NSPLIT; sp++)
        mg = fmaxf(mg, g_part_m[(bh*NSPLIT + sp)*QL + i]);

    float L = 0.f;
    float4 acc = make_float4(0.f, 0.f, 0.f, 0.f);
#pragma unroll
    for (int sp = 0; sp < NSPLIT; sp++) {
        const int pi = (bh*NSPLIT + sp)*QL + i;
        const float wgt = __expf(g_part_m[pi] - mg);
        L += g_part_l[pi] * wgt;
        const float4 a = *(const float4*)&g_part_acc[(size_t)pi*HDIM + dg*4];
        acc.x += a.x * wgt; acc.y += a.y * wgt; acc.z += a.z * wgt; acc.w += a.w * wgt;
    }
    const float inv = 1.f / L;
    const float v[4] = {acc.x*inv, acc.y*inv, acc.z*inv, acc.w*inv};
#pragma unroll
    for (int k = 0; k < 4; k++) {
        const int d = dg*4 + k;
        g_mid[b*(QL*HID) + (d >> 2)*HID + (d & 3)*256 + i*16 + h] = v[k];
    }
}

// ============================================================
// Kernel 4a: output projection split-K partial.
// ============================================================
__global__ __launch_bounds__(256) void oproj_part_kernel(
    const float* __restrict__ Wo)
{
    __shared__ float As[64][17];
    __shared__ float Ws[64][17];

    const int tid = threadIdx.x;
    const int tx = tid & 15, ty = tid >> 4;
    const int col0 = blockIdx.x * 64;
    const int row0 = blockIdx.y * 64;
    const int ks   = blockIdx.z;

    float acc[4][4];
#pragma unroll
    for (int r = 0; r < 4; r++)
#pragma unroll
        for (int c = 0; c < 4; c++) acc[r][c] = 0.f;

    const int lr = tid >> 2;
    const int lk = (tid & 3) * 4;
    const float* Arow = g_mid + (size_t)(row0 + lr) * HID + ks*KSLICE + lk;
    const float* Wrow = Wo    + (size_t)(col0 + lr) * HID + ks*KSLICE + lk;

    float4 a4 = *(const float4*)Arow;
    float4 w4 = *(const float4*)Wrow;

    for (int t = 0; t < KSLICE/16; t++) {
        As[lr][lk] = a4.x; As[lr][lk+1] = a4.y; As[lr][lk+2] = a4.z; As[lr][lk+3] = a4.w;
        Ws[lr][lk] = w4.x; Ws[lr][lk+1] = w4.y; Ws[lr][lk+2] = w4.z; Ws[lr][lk+3] = w4.w;
        __syncthreads();
        if (t < KSLICE/16 - 1) {
            a4 = *(const float4*)(Arow + (t+1)*16);
            w4 = *(const float4*)(Wrow + (t+1)*16);
        }
#pragma unroll
        for (int kk = 0; kk < 16; kk++) {
            float av[4], wv[4];
#pragma unroll
            for (int r = 0; r < 4; r++) av[r] = As[ty*4 + r][kk];
#pragma unroll
            for (int c = 0; c < 4; c++) wv[c] = Ws[tx*4 + c][kk];
#pragma unroll
            for (int r = 0; r < 4; r++)
#pragma unroll
                for (int c = 0; c < 4; c++) acc[r][c] += av[r] * wv[c];
        }
        __syncthreads();
    }

#pragma unroll
    for (int r = 0; r < 4; r++) {
        const int m = row0 + ty*4 + r;
        float4 o = make_float4(acc[r][0], acc[r][1], acc[r][2], acc[r][3]);
        *(float4*)&g_op_pp[((size_t)ks*128 + m)*HID + col0 + tx*4] = o;
    }
}

// ============================================================
// Kernel 4b: reduce oproj partials + bias -> out.
// ============================================================
__global__ __launch_bounds__(256) void oproj_reduce_kernel(
    const float* __restrict__ bo, float* __restrict__ out)
{
    const int idx = blockIdx.x * 256 + threadIdx.x;
    const int m = idx >> 8;
    const int n = (idx & 255) * 4;
    const size_t base = (size_t)m*HID + n;

    float4 s = *(const float4*)&g_op_pp[base];
#pragma unroll
    for (int ks = 1; ks < KSPLIT; ks++) {
        float4 p = *(const float4*)&g_op_pp[(size_t)ks*128*HID + base];
        s.x += p.x; s.y += p.y; s.z += p.z; s.w += p.w;
    }
    s.x += bo[n]; s.y += bo[n+1]; s.z += bo[n+2]; s.w += bo[n+3];
    *(float4*)&out[base] = s;
}

// ============================================================
extern "C" void kernel_launch(void* const* d_in, const int* in_sizes, int n_in,
                              void* d_out, int out_size)
{
    const float* hidden  = (const float*)d_in[0];
    const float* past_k  = (const float*)d_in[1];
    const float* past_v  = (const float*)d_in[2];
    // d_in[3] causal_mask: computed analytically (j > PASTLEN + i)
    const float* padmask = (const float*)d_in[4];
    const float* Wq = (const float*)d_in[5];
    const float* bq = (const float*)d_in[6];
    const float* Wk = (const float*)d_in[7];
    const float* bk = (const float*)d_in[8];
    const float* Wv = (const float*)d_in[9];
    const float* bv = (const float*)d_in[10];
    const float* Wo = (const float*)d_in[11];
    const float* bo = (const float*)d_in[12];
    float* out = (float*)d_out;

    cudaFuncSetAttribute(attn_mma_kernel,
                         cudaFuncAttributeMaxDynamicSharedMemorySize, ATTN_SMEM);

    qkv_part_kernel<<<dim3(48, 2, KSPLIT), 256>>>(hidden, Wq, Wk, Wv);
    qkv_reduce_kernel<<<384, 256>>>(bq, bk, bv);
    attn_mma_kernel<<<BB*NHAT*NSPLIT, 256, ATTN_SMEM>>>(past_k, past_v, padmask);
    combine_kernel<<<BB*NHAT, 256>>>();
    oproj_part_kernel<<<dim3(16, 2, KSPLIT), 256>>>(Wo);
    oproj_reduce_kernel<<<128, 256>>>(bo, out);
}